// round 9
// baseline (speedup 1.0000x reference)
#include <cuda_runtime.h>
#include <cuda_bf16.h>
#include <cstdint>

// ---------------------------------------------------------------------------
// Problem constants
// ---------------------------------------------------------------------------
#define BROWS 32768
#define NUM_EXPERTS 10
#define NUM_LEVELS 4
#define CBK 256
#define ZD 128
#define BETA 0.001f

// Output layout (float32, tuple flattened: out, loss, indices, x_q)
#define OUT_OFF  0
#define LOSS_OFF (32768 * 768)
#define IDX_OFF  (LOSS_OFF + 1)
#define XQ_OFF   (IDX_OFF + 32768 * 4)

// ---------------------------------------------------------------------------
// Device scratch
// ---------------------------------------------------------------------------
__device__ float g_buf0[32768u * 2048u];   // encoder ping
__device__ float g_buf1[32768u * 1024u];   // encoder pong
__device__ float g_res [32768 * ZD];
__device__ float g_xq  [32768 * ZD];
__device__ float g_lossbuf[32768];
__device__ int   g_counts[NUM_EXPERTS];
__device__ int   g_cursor[NUM_EXPERTS];
__device__ int   g_offsets[NUM_EXPERTS + 1];
__device__ int   g_perm[32768];

// decoder bf16 hi/lo activation ping-pong + pre-split transposed weights
__device__ __nv_bfloat16 g_dA0[32768u * 1024u];
__device__ __nv_bfloat16 g_dA1[32768u * 1024u];
__device__ __nv_bfloat16 g_dB0[32768u * 2048u];
__device__ __nv_bfloat16 g_dB1[32768u * 2048u];
#define W_TOTAL 4259840
__device__ __nv_bfloat16 g_dw0[W_TOTAL];
__device__ __nv_bfloat16 g_dw1[W_TOTAL];

// ---------------------------------------------------------------------------
// PTX helpers (arch-portable)
// ---------------------------------------------------------------------------
__device__ __forceinline__ uint32_t smem_u32(const void* p) {
    uint32_t a;
    asm("{ .reg .u64 t; cvta.to.shared.u64 t, %1; cvt.u32.u64 %0, t; }"
        : "=r"(a) : "l"(p));
    return a;
}
__device__ __forceinline__ void cpa16(uint32_t dst, const void* src) {
    asm volatile("cp.async.cg.shared.global [%0], [%1], 16;" :: "r"(dst), "l"(src) : "memory");
}
#define CP_COMMIT() asm volatile("cp.async.commit_group;" ::: "memory")

#define LDSM4(r0, r1, r2, r3, addr) \
    asm volatile("ldmatrix.sync.aligned.m8n8.x4.shared.b16 {%0,%1,%2,%3}, [%4];" \
        : "=r"(r0), "=r"(r1), "=r"(r2), "=r"(r3) : "r"(addr))

#define MMA16816(acc, a, b0, b1) \
    asm volatile("mma.sync.aligned.m16n8k16.row.col.f32.bf16.bf16.f32 " \
        "{%0,%1,%2,%3}, {%4,%5,%6,%7}, {%8,%9}, {%0,%1,%2,%3};" \
        : "+f"((acc)[0]), "+f"((acc)[1]), "+f"((acc)[2]), "+f"((acc)[3]) \
        : "r"((a)[0]), "r"((a)[1]), "r"((a)[2]), "r"((a)[3]), "r"(b0), "r"(b1))

// ---------------------------------------------------------------------------
// fp32 SIMT SGEMM v2 — ENCODER (flip-critical; bitwise-identical math to R1:
// each output element accumulates identical FFMAs in ascending-k order).
// BK=16, double-buffered smem, register prefetch, 1 sync per chunk.
// ---------------------------------------------------------------------------
template <bool RELU>
__global__ __launch_bounds__(256, 2)
void sgemm_db(const float* __restrict__ A, const float* __restrict__ W,
              const float* __restrict__ bias, float* __restrict__ C,
              int M, int N, int K)
{
    __shared__ float As[2][16][128];   // [stage][k][row]
    __shared__ float Bs[2][16][128];   // [stage][k][col]

    const int t  = threadIdx.x;
    const int bm = blockIdx.y;
    const int bn = blockIdx.x;
    const int tx = t & 15;
    const int ty = t >> 4;

    // A loaders: 128 rows x 16 k = 512 float4; thread t -> f4 idx {t, t+256}
    const int ar0 = t >> 2;            // 0..63
    const int akq = (t & 3) * 4;       // 0,4,8,12
    // B loaders: 16 k x 128 cols = 512 float4; thread t -> {t, t+256}
    const int bk0 = t >> 5;            // 0..7
    const int bcq = (t & 31) * 4;      // 0..124

    const float* Ag = A + (size_t)(bm * 128) * K;
    const float* Wg = W + bn * 128;

    float acc[8][8];
#pragma unroll
    for (int i = 0; i < 8; i++)
#pragma unroll
        for (int j = 0; j < 8; j++) acc[i][j] = 0.f;

    const int nch = K >> 4;

    // prologue: prefetch chunk 0
    float4 pa0 = *(const float4*)(Ag + (size_t)ar0 * K + akq);
    float4 pa1 = *(const float4*)(Ag + (size_t)(64 + ar0) * K + akq);
    float4 pb0 = *(const float4*)(Wg + (size_t)bk0 * N + bcq);
    float4 pb1 = *(const float4*)(Wg + (size_t)(8 + bk0) * N + bcq);

    for (int ch = 0; ch < nch; ch++) {
        const int s = ch & 1;
        // store prefetched chunk (A transposed)
        As[s][akq + 0][ar0] = pa0.x;
        As[s][akq + 1][ar0] = pa0.y;
        As[s][akq + 2][ar0] = pa0.z;
        As[s][akq + 3][ar0] = pa0.w;
        As[s][akq + 0][64 + ar0] = pa1.x;
        As[s][akq + 1][64 + ar0] = pa1.y;
        As[s][akq + 2][64 + ar0] = pa1.z;
        As[s][akq + 3][64 + ar0] = pa1.w;
        *(float4*)&Bs[s][bk0][bcq]     = pb0;
        *(float4*)&Bs[s][8 + bk0][bcq] = pb1;
        __syncthreads();

        // prefetch next chunk (latency hidden behind compute below)
        if (ch + 1 < nch) {
            const int k0 = (ch + 1) << 4;
            pa0 = *(const float4*)(Ag + (size_t)ar0 * K + k0 + akq);
            pa1 = *(const float4*)(Ag + (size_t)(64 + ar0) * K + k0 + akq);
            pb0 = *(const float4*)(Wg + (size_t)(k0 + bk0) * N + bcq);
            pb1 = *(const float4*)(Wg + (size_t)(k0 + 8 + bk0) * N + bcq);
        }

#pragma unroll
        for (int k = 0; k < 16; k++) {
            float a[8], b[8];
            *(float4*)&a[0] = *(const float4*)&As[s][k][ty * 8];
            *(float4*)&a[4] = *(const float4*)&As[s][k][ty * 8 + 4];
            *(float4*)&b[0] = *(const float4*)&Bs[s][k][tx * 8];
            *(float4*)&b[4] = *(const float4*)&Bs[s][k][tx * 8 + 4];
#pragma unroll
            for (int i = 0; i < 8; i++)
#pragma unroll
                for (int j = 0; j < 8; j++)
                    acc[i][j] += a[i] * b[j];
        }
        // no second sync: next store targets the other buffer; the sync at the
        // top of the NEXT iteration orders compute(s) before store(s) two
        // iterations later.
    }

    const int crow0 = bm * 128 + ty * 8;
    const int ccol0 = bn * 128 + tx * 8;
    float bb[8];
#pragma unroll
    for (int j = 0; j < 8; j++) bb[j] = bias[ccol0 + j];

#pragma unroll
    for (int i = 0; i < 8; i++) {
        float v[8];
#pragma unroll
        for (int j = 0; j < 8; j++) {
            float x = acc[i][j] + bb[j];
            if (RELU) x = fmaxf(x, 0.f);
            v[j] = x;
        }
        float* cp = C + (size_t)(crow0 + i) * N + ccol0;
        *(float4*)(cp)     = *(float4*)&v[0];
        *(float4*)(cp + 4) = *(float4*)&v[4];
    }
}

// ---------------------------------------------------------------------------
// HMMA bf16x3 GEMM — DECODER (math bitwise = R7's proven decoder).
// STAGES-deep cp.async pipeline. CTA 128x128, BK=32, 256 threads.
// ---------------------------------------------------------------------------
#define TSTRIDE 40
#define SUBTILE (128 * TSTRIDE * 2)      // 10240 B

template <int STAGES, bool RELU, int OMODE>
__global__ __launch_bounds__(256)
void hmma_gemm(const __nv_bfloat16* __restrict__ A0, const __nv_bfloat16* __restrict__ A1,
               const __nv_bfloat16* __restrict__ B0, const __nv_bfloat16* __restrict__ B1,
               const float* __restrict__ bias, float* __restrict__ Cf,
               __nv_bfloat16* __restrict__ C0, __nv_bfloat16* __restrict__ C1,
               int M, int N, int K)
{
    constexpr int STAGE = 4 * SUBTILE;
    extern __shared__ char smem[];
    const uint32_t sbase = smem_u32(smem);

    const int tid  = threadIdx.x;
    const int lane = tid & 31;
    const int wid  = tid >> 5;
    const int wm   = wid & 3;
    const int wn   = wid >> 2;
    const int m0   = blockIdx.y * 128;
    const int n0   = blockIdx.x * 128;
    const int nch  = K >> 5;

    float acc[2][8][4];
#pragma unroll
    for (int a = 0; a < 2; a++)
#pragma unroll
        for (int b = 0; b < 8; b++)
#pragma unroll
            for (int c = 0; c < 4; c++) acc[a][b][c] = 0.f;

    auto load_stage = [&](int stg, int k0) {
        const uint32_t sb_ = sbase + stg * STAGE;
#pragma unroll
        for (int ii = 0; ii < 2; ii++) {
            const int i = tid + ii * 256;
            const int r = i >> 2, c = i & 3;
            const uint32_t so = r * 80 + c * 16;
            const size_t ga = (size_t)(m0 + r) * K + k0 + c * 8;
            const size_t gb = (size_t)(n0 + r) * K + k0 + c * 8;
            cpa16(sb_ + so,               A0 + ga);
            cpa16(sb_ + SUBTILE + so,     A1 + ga);
            cpa16(sb_ + 2 * SUBTILE + so, B0 + gb);
            cpa16(sb_ + 3 * SUBTILE + so, B1 + gb);
        }
    };

#pragma unroll
    for (int s = 0; s < STAGES; s++) {
        if (s < nch) load_stage(s, s * 32);
        CP_COMMIT();
    }

    const int lrow = lane & 15;
    const int lsel = (lane >> 4) << 3;

    for (int ch = 0; ch < nch; ch++) {
        asm volatile("cp.async.wait_group %0;" :: "n"(STAGES - 1) : "memory");
        __syncthreads();
        const uint32_t sb = sbase + (ch % STAGES) * STAGE;
        const uint32_t Ahb = sb, Alb = sb + SUBTILE;
        const uint32_t Bhb = sb + 2 * SUBTILE, Blb = sb + 3 * SUBTILE;

#pragma unroll
        for (int kk = 0; kk < 32; kk += 16) {
            uint32_t ah[2][4], al[2][4];
#pragma unroll
            for (int mt = 0; mt < 2; mt++) {
                uint32_t off = ((wm * 32 + mt * 16 + lrow) * TSTRIDE + kk + lsel) * 2;
                LDSM4(ah[mt][0], ah[mt][1], ah[mt][2], ah[mt][3], Ahb + off);
                LDSM4(al[mt][0], al[mt][1], al[mt][2], al[mt][3], Alb + off);
            }
            uint32_t bh[8][2], bl[8][2];
#pragma unroll
            for (int g = 0; g < 4; g++) {
                uint32_t off = ((wn * 64 + g * 16 + lrow) * TSTRIDE + kk + lsel) * 2;
                uint32_t t0, t1, t2, t3;
                LDSM4(t0, t1, t2, t3, Bhb + off);
                bh[2*g][0] = t0;   bh[2*g][1] = t2;
                bh[2*g+1][0] = t1; bh[2*g+1][1] = t3;
                LDSM4(t0, t1, t2, t3, Blb + off);
                bl[2*g][0] = t0;   bl[2*g][1] = t2;
                bl[2*g+1][0] = t1; bl[2*g+1][1] = t3;
            }
            // 3-pass: hh + hl + lh (same order as validated R7 kernel)
#pragma unroll
            for (int mt = 0; mt < 2; mt++)
#pragma unroll
                for (int nt = 0; nt < 8; nt++) {
                    MMA16816(acc[mt][nt], ah[mt], bh[nt][0], bh[nt][1]);
                    MMA16816(acc[mt][nt], ah[mt], bl[nt][0], bl[nt][1]);
                    MMA16816(acc[mt][nt], al[mt], bh[nt][0], bh[nt][1]);
                }
        }
        __syncthreads();
        if (ch + STAGES < nch) load_stage(ch % STAGES, (ch + STAGES) * 32);
        CP_COMMIT();
    }

    // ---- epilogue ----
    const int gid = lane >> 2;
    const int tg  = lane & 3;
#pragma unroll
    for (int mt = 0; mt < 2; mt++) {
#pragma unroll
        for (int nt = 0; nt < 8; nt++) {
            const int col = n0 + wn * 64 + nt * 8 + tg * 2;
            const float2 bb = __ldg((const float2*)(bias + col));
#pragma unroll
            for (int h = 0; h < 2; h++) {
                const int row = m0 + wm * 32 + mt * 16 + gid + h * 8;
                float v0 = acc[mt][nt][2*h]   + bb.x;
                float v1 = acc[mt][nt][2*h+1] + bb.y;
                if (RELU) { v0 = fmaxf(v0, 0.f); v1 = fmaxf(v1, 0.f); }
                if (OMODE == 0) {
                    *(float2*)(Cf + (size_t)row * N + col) = make_float2(v0, v1);
                } else {
                    __nv_bfloat16 h0 = __float2bfloat16(v0);
                    __nv_bfloat16 h1 = __float2bfloat16(v1);
                    __nv_bfloat162 p0; p0.x = h0; p0.y = h1;
                    __nv_bfloat162 p1;
                    p1.x = __float2bfloat16(v0 - __bfloat162float(h0));
                    p1.y = __float2bfloat16(v1 - __bfloat162float(h1));
                    *(__nv_bfloat162*)(C0 + (size_t)row * N + col) = p0;
                    *(__nv_bfloat162*)(C1 + (size_t)row * N + col) = p1;
                }
            }
        }
    }
}

// ---------------------------------------------------------------------------
// Preprocessing: weight transpose + bf16 split; activation split
// ---------------------------------------------------------------------------
__global__ void k_wprep2(const float* __restrict__ W, __nv_bfloat16* __restrict__ T0,
                         __nv_bfloat16* __restrict__ T1, int K, int N)
{
    __shared__ float t[32][33];
    int n = blockIdx.x * 32 + threadIdx.x;
    int k = blockIdx.y * 32 + threadIdx.y;
    t[threadIdx.y][threadIdx.x] = W[(size_t)k * N + n];
    __syncthreads();
    int nn = blockIdx.x * 32 + threadIdx.y;
    int kk = blockIdx.y * 32 + threadIdx.x;
    float v = t[threadIdx.x][threadIdx.y];
    __nv_bfloat16 h = __float2bfloat16(v);
    T0[(size_t)nn * K + kk] = h;
    T1[(size_t)nn * K + kk] = __float2bfloat16(v - __bfloat162float(h));
}

__global__ void k_split2(const float* __restrict__ src, __nv_bfloat16* __restrict__ o0,
                         __nv_bfloat16* __restrict__ o1, int n)
{
    int i = blockIdx.x * 256 + threadIdx.x;
    if (i < n) {
        float v = src[i];
        __nv_bfloat16 h = __float2bfloat16(v);
        o0[i] = h;
        o1[i] = __float2bfloat16(v - __bfloat162float(h));
    }
}

// ---------------------------------------------------------------------------
// Expert counting-sort
// ---------------------------------------------------------------------------
__global__ void k_zero_counts() {
    int t = threadIdx.x;
    if (t < NUM_EXPERTS) { g_counts[t] = 0; g_cursor[t] = 0; }
}
__global__ void k_hist(const int* __restrict__ labels) {
    int i = blockIdx.x * blockDim.x + threadIdx.x;
    if (i < BROWS) atomicAdd(&g_counts[labels[i]], 1);
}
__global__ void k_scan() {
    if (threadIdx.x == 0) {
        int s = 0;
        for (int e = 0; e < NUM_EXPERTS; e++) { g_offsets[e] = s; s += g_counts[e]; }
        g_offsets[NUM_EXPERTS] = s;
    }
}
__global__ void k_scatter(const int* __restrict__ labels) {
    int i = blockIdx.x * blockDim.x + threadIdx.x;
    if (i < BROWS) {
        int e = labels[i];
        int p = atomicAdd(&g_cursor[e], 1);
        g_perm[g_offsets[e] + p] = i;
    }
}
__global__ void k_rq_init() {
    int i = blockIdx.x * blockDim.x + threadIdx.x;
    if (i < BROWS * ZD) g_xq[i] = 0.f;
    if (i < BROWS)      g_lossbuf[i] = 0.f;
}

// ---------------------------------------------------------------------------
// Residual quantization (validated round 1)
// ---------------------------------------------------------------------------
__global__ void rq_level(const float* __restrict__ cb,
                         float* __restrict__ idx_out, int level)
{
    extern __shared__ float c_sh[];        // 256 * 129 floats
    __shared__ float res_sh[ZD];
    __shared__ float cn_sh[CBK];
    __shared__ float s_sc[CBK];
    __shared__ int   s_ix[CBK];
    __shared__ float s_red[4];
    __shared__ int   s_kmin;

    const int e     = blockIdx.y;
    const int start = g_offsets[e];
    const int end   = g_offsets[e + 1];
    const int rbase = start + blockIdx.x * 32;
    if (rbase >= end) return;

    const int t = threadIdx.x;
    const float* cbl = cb + ((size_t)level * NUM_EXPERTS + e) * CBK * ZD;
    for (int i = t; i < (CBK * ZD) / 4; i += 256) {
        float4 v = ((const float4*)cbl)[i];
        int k = i >> 5;
        int j = (i & 31) << 2;
        float* d = &c_sh[k * 129 + j];
        d[0] = v.x; d[1] = v.y; d[2] = v.z; d[3] = v.w;
    }
    __syncthreads();

    {
        const float* cr = &c_sh[t * 129];
        float s = 0.f;
#pragma unroll 8
        for (int j = 0; j < ZD; j++) s += cr[j] * cr[j];
        cn_sh[t] = s;
    }
    __syncthreads();

    const int nrows = min(32, end - rbase);
    for (int i = 0; i < nrows; i++) {
        const int row = g_perm[rbase + i];
        if (t < ZD) res_sh[t] = g_res[row * ZD + t];
        __syncthreads();

        float dot = 0.f;
        const float* cr = &c_sh[t * 129];
#pragma unroll 8
        for (int j = 0; j < ZD; j++) dot += cr[j] * res_sh[j];
        s_sc[t] = cn_sh[t] - 2.f * dot;
        s_ix[t] = t;
        __syncthreads();

#pragma unroll
        for (int s = 128; s > 0; s >>= 1) {
            if (t < s) {
                float sc2 = s_sc[t + s]; int ix2 = s_ix[t + s];
                if (sc2 < s_sc[t] || (sc2 == s_sc[t] && ix2 < s_ix[t])) {
                    s_sc[t] = sc2; s_ix[t] = ix2;
                }
            }
            __syncthreads();
        }
        if (t == 0) s_kmin = s_ix[0];
        __syncthreads();
        const int kmin = s_kmin;

        float sq = 0.f;
        if (t < ZD) {
            float q  = c_sh[kmin * 129 + t];
            float nr = res_sh[t] - q;
            g_res[row * ZD + t] = nr;
            g_xq [row * ZD + t] += q;
            sq = nr * nr;
        }
#pragma unroll
        for (int o = 16; o > 0; o >>= 1) sq += __shfl_down_sync(0xffffffffu, sq, o);
        if (t < ZD && (t & 31) == 0) s_red[t >> 5] = sq;
        __syncthreads();
        if (t == 0) {
            g_lossbuf[row] += s_red[0] + s_red[1] + s_red[2] + s_red[3];
            idx_out[row * 4 + level] = (float)kmin;
        }
        __syncthreads();
    }
}

__global__ void k_loss_finish(float* __restrict__ loss_out) {
    __shared__ float sm[1024];
    float s = 0.f;
    for (int i = threadIdx.x; i < BROWS; i += 1024) s += g_lossbuf[i];
    sm[threadIdx.x] = s;
    __syncthreads();
    for (int k = 512; k > 0; k >>= 1) {
        if (threadIdx.x < k) sm[threadIdx.x] += sm[threadIdx.x + k];
        __syncthreads();
    }
    if (threadIdx.x == 0)
        loss_out[0] = sm[0] * (1.f + BETA) / ((float)BROWS * (float)ZD);
}

__global__ void k_copy_xq(float* __restrict__ dst) {
    int i = blockIdx.x * blockDim.x + threadIdx.x;
    if (i < BROWS * ZD) dst[i] = g_xq[i];
}

// ---------------------------------------------------------------------------
// Host launch
// ---------------------------------------------------------------------------
template <bool RELU>
static void launch_sgemm(const float* A, const float* W, const float* b, float* C,
                         int M, int N, int K)
{
    dim3 grid(N / 128, M / 128);
    sgemm_db<RELU><<<grid, 256>>>(A, W, b, C, M, N, K);
}

template <int STAGES, bool RELU, int OMODE>
static void launch_hmma(const __nv_bfloat16* a0, const __nv_bfloat16* a1,
                        const __nv_bfloat16* b0, const __nv_bfloat16* b1,
                        const float* bias, float* cf,
                        __nv_bfloat16* c0, __nv_bfloat16* c1,
                        int M, int N, int K)
{
    constexpr int SMEMB = STAGES * 4 * SUBTILE;
    cudaFuncSetAttribute(hmma_gemm<STAGES, RELU, OMODE>,
                         cudaFuncAttributeMaxDynamicSharedMemorySize, SMEMB);
    dim3 g(N / 128, M / 128);
    hmma_gemm<STAGES, RELU, OMODE><<<g, 256, SMEMB>>>(
        a0, a1, b0, b1, bias, cf, c0, c1, M, N, K);
}

extern "C" void kernel_launch(void* const* d_in, const int* in_sizes, int n_in,
                              void* d_out, int out_size)
{
    const float* x      = (const float*)d_in[0];
    const int*   labels = (const int*)  d_in[1];
    const float* ew[4]  = {(const float*)d_in[2], (const float*)d_in[4],
                           (const float*)d_in[6], (const float*)d_in[8]};
    const float* eb[4]  = {(const float*)d_in[3], (const float*)d_in[5],
                           (const float*)d_in[7], (const float*)d_in[9]};
    const float* dw[4]  = {(const float*)d_in[10], (const float*)d_in[12],
                           (const float*)d_in[14], (const float*)d_in[16]};
    const float* db[4]  = {(const float*)d_in[11], (const float*)d_in[13],
                           (const float*)d_in[15], (const float*)d_in[17]};
    const float* cb     = (const float*)d_in[18];
    float* out = (float*)d_out;

    float *buf0, *buf1, *res, *xq;
    __nv_bfloat16 *dA0, *dA1, *dB0, *dB1, *dw0, *dw1;
    cudaGetSymbolAddress((void**)&buf0, g_buf0);
    cudaGetSymbolAddress((void**)&buf1, g_buf1);
    cudaGetSymbolAddress((void**)&res,  g_res);
    cudaGetSymbolAddress((void**)&xq,   g_xq);
    cudaGetSymbolAddress((void**)&dA0,  g_dA0);
    cudaGetSymbolAddress((void**)&dA1,  g_dA1);
    cudaGetSymbolAddress((void**)&dB0,  g_dB0);
    cudaGetSymbolAddress((void**)&dB1,  g_dB1);
    cudaGetSymbolAddress((void**)&dw0,  g_dw0);
    cudaGetSymbolAddress((void**)&dw1,  g_dw1);

    static const int RQ_SMEM = CBK * 129 * sizeof(float);
    cudaFuncSetAttribute(rq_level, cudaFuncAttributeMaxDynamicSharedMemorySize, RQ_SMEM);

    // decoder weight table ([N,K] after transpose)
    const int dLN[4] = {512, 1024, 2048, 768};
    const int dLK[4] = {128, 512, 1024, 2048};
    size_t doff[4];
    {
        size_t o = 0;
        for (int i = 0; i < 4; i++) { doff[i] = o; o += (size_t)dLN[i] * dLK[i]; }
    }

    // ---- preprocess decoder weights ----
    for (int i = 0; i < 4; i++) {
        dim3 gd(dLN[i] / 32, dLK[i] / 32), b(32, 32);
        k_wprep2<<<gd, b>>>(dw[i], dw0 + doff[i], dw1 + doff[i], dLK[i], dLN[i]);
    }

    // ---- expert grouping ----
    k_zero_counts<<<1, 32>>>();
    k_hist   <<<BROWS / 256, 256>>>(labels);
    k_scan   <<<1, 1>>>();
    k_scatter<<<BROWS / 256, 256>>>(labels);

    // ---- encoder (fp32 SIMT v2 — bitwise-identical z to round 1) ----
    launch_sgemm<true >(x,    ew[0], eb[0], buf0, BROWS, 2048, 768);
    launch_sgemm<true >(buf0, ew[1], eb[1], buf1, BROWS, 1024, 2048);
    launch_sgemm<true >(buf1, ew[2], eb[2], buf0, BROWS, 512,  1024);
    launch_sgemm<false>(buf0, ew[3], eb[3], res,  BROWS, 128,  512);

    // ---- residual quantization ----
    k_rq_init<<<(BROWS * ZD + 255) / 256, 256>>>();
    dim3 rqg((BROWS + 31) / 32, NUM_EXPERTS);
    for (int l = 0; l < NUM_LEVELS; l++)
        rq_level<<<rqg, 256, RQ_SMEM>>>(cb, out + IDX_OFF, l);
    k_loss_finish<<<1, 1024>>>(out + LOSS_OFF);
    k_copy_xq<<<(BROWS * ZD + 255) / 256, 256>>>(out + XQ_OFF);

    // ---- decoder (bf16x3 HMMA, 4-stage pipeline) ----
    k_split2<<<(BROWS * ZD + 255) / 256, 256>>>(xq, dA0, dA1, BROWS * ZD);
    launch_hmma<4, true, 1>(dA0, dA1, dw0 + doff[0], dw1 + doff[0], db[0],
                            nullptr, dB0, dB1, BROWS, 512, 128);
    launch_hmma<4, true, 1>(dB0, dB1, dw0 + doff[1], dw1 + doff[1], db[1],
                            nullptr, dA0, dA1, BROWS, 1024, 512);
    launch_hmma<4, true, 1>(dA0, dA1, dw0 + doff[2], dw1 + doff[2], db[2],
                            nullptr, dB0, dB1, BROWS, 2048, 1024);
    launch_hmma<4, false, 0>(dB0, dB1, dw0 + doff[3], dw1 + doff[3], db[3],
                             out + OUT_OFF, nullptr, nullptr, BROWS, 768, 2048);
}

// round 10
// speedup vs baseline: 1.0380x; 1.0380x over previous
#include <cuda_runtime.h>
#include <cuda_bf16.h>
#include <cstdint>

// ---------------------------------------------------------------------------
// Problem constants
// ---------------------------------------------------------------------------
#define BROWS 32768
#define NUM_EXPERTS 10
#define NUM_LEVELS 4
#define CBK 256
#define ZD 128
#define BETA 0.001f

// Output layout (float32, tuple flattened: out, loss, indices, x_q)
#define OUT_OFF  0
#define LOSS_OFF (32768 * 768)
#define IDX_OFF  (LOSS_OFF + 1)
#define XQ_OFF   (IDX_OFF + 32768 * 4)

// ---------------------------------------------------------------------------
// Device scratch
// ---------------------------------------------------------------------------
__device__ float g_buf0[32768u * 2048u];   // encoder ping
__device__ float g_buf1[32768u * 1024u];   // encoder pong
__device__ float g_res [32768 * ZD];
__device__ float g_xq  [32768 * ZD];
__device__ float g_lossbuf[32768];
__device__ int   g_counts[NUM_EXPERTS];
__device__ int   g_cursor[NUM_EXPERTS];
__device__ int   g_offsets[NUM_EXPERTS + 1];
__device__ int   g_perm[32768];

// decoder bf16 hi/lo activation ping-pong + pre-split transposed weights
__device__ __nv_bfloat16 g_dA0[32768u * 1024u];
__device__ __nv_bfloat16 g_dA1[32768u * 1024u];
__device__ __nv_bfloat16 g_dB0[32768u * 2048u];
__device__ __nv_bfloat16 g_dB1[32768u * 2048u];
#define W_TOTAL 4259840
__device__ __nv_bfloat16 g_dw0[W_TOTAL];
__device__ __nv_bfloat16 g_dw1[W_TOTAL];

// ---------------------------------------------------------------------------
// PTX helpers (arch-portable)
// ---------------------------------------------------------------------------
__device__ __forceinline__ uint32_t smem_u32(const void* p) {
    uint32_t a;
    asm("{ .reg .u64 t; cvta.to.shared.u64 t, %1; cvt.u32.u64 %0, t; }"
        : "=r"(a) : "l"(p));
    return a;
}
__device__ __forceinline__ void cpa16(uint32_t dst, const void* src) {
    asm volatile("cp.async.cg.shared.global [%0], [%1], 16;" :: "r"(dst), "l"(src) : "memory");
}
#define CP_COMMIT() asm volatile("cp.async.commit_group;" ::: "memory")

#define LDSM4(r0, r1, r2, r3, addr) \
    asm volatile("ldmatrix.sync.aligned.m8n8.x4.shared.b16 {%0,%1,%2,%3}, [%4];" \
        : "=r"(r0), "=r"(r1), "=r"(r2), "=r"(r3) : "r"(addr))

#define MMA16816(acc, a, b0, b1) \
    asm volatile("mma.sync.aligned.m16n8k16.row.col.f32.bf16.bf16.f32 " \
        "{%0,%1,%2,%3}, {%4,%5,%6,%7}, {%8,%9}, {%0,%1,%2,%3};" \
        : "+f"((acc)[0]), "+f"((acc)[1]), "+f"((acc)[2]), "+f"((acc)[3]) \
        : "r"((a)[0]), "r"((a)[1]), "r"((a)[2]), "r"((a)[3]), "r"(b0), "r"(b1))

// ---------------------------------------------------------------------------
// fp32 SIMT SGEMM v2 — ENCODER (bitwise-identical z to round 1).
// BK=16, double-buffered smem, register prefetch, 1 sync per chunk.
// ---------------------------------------------------------------------------
template <bool RELU>
__global__ __launch_bounds__(256, 2)
void sgemm_db(const float* __restrict__ A, const float* __restrict__ W,
              const float* __restrict__ bias, float* __restrict__ C,
              int M, int N, int K)
{
    __shared__ float As[2][16][128];   // [stage][k][row]
    __shared__ float Bs[2][16][128];   // [stage][k][col]

    const int t  = threadIdx.x;
    const int bm = blockIdx.y;
    const int bn = blockIdx.x;
    const int tx = t & 15;
    const int ty = t >> 4;

    const int ar0 = t >> 2;            // 0..63
    const int akq = (t & 3) * 4;       // 0,4,8,12
    const int bk0 = t >> 5;            // 0..7
    const int bcq = (t & 31) * 4;      // 0..124

    const float* Ag = A + (size_t)(bm * 128) * K;
    const float* Wg = W + bn * 128;

    float acc[8][8];
#pragma unroll
    for (int i = 0; i < 8; i++)
#pragma unroll
        for (int j = 0; j < 8; j++) acc[i][j] = 0.f;

    const int nch = K >> 4;

    float4 pa0 = *(const float4*)(Ag + (size_t)ar0 * K + akq);
    float4 pa1 = *(const float4*)(Ag + (size_t)(64 + ar0) * K + akq);
    float4 pb0 = *(const float4*)(Wg + (size_t)bk0 * N + bcq);
    float4 pb1 = *(const float4*)(Wg + (size_t)(8 + bk0) * N + bcq);

    for (int ch = 0; ch < nch; ch++) {
        const int s = ch & 1;
        As[s][akq + 0][ar0] = pa0.x;
        As[s][akq + 1][ar0] = pa0.y;
        As[s][akq + 2][ar0] = pa0.z;
        As[s][akq + 3][ar0] = pa0.w;
        As[s][akq + 0][64 + ar0] = pa1.x;
        As[s][akq + 1][64 + ar0] = pa1.y;
        As[s][akq + 2][64 + ar0] = pa1.z;
        As[s][akq + 3][64 + ar0] = pa1.w;
        *(float4*)&Bs[s][bk0][bcq]     = pb0;
        *(float4*)&Bs[s][8 + bk0][bcq] = pb1;
        __syncthreads();

        if (ch + 1 < nch) {
            const int k0 = (ch + 1) << 4;
            pa0 = *(const float4*)(Ag + (size_t)ar0 * K + k0 + akq);
            pa1 = *(const float4*)(Ag + (size_t)(64 + ar0) * K + k0 + akq);
            pb0 = *(const float4*)(Wg + (size_t)(k0 + bk0) * N + bcq);
            pb1 = *(const float4*)(Wg + (size_t)(k0 + 8 + bk0) * N + bcq);
        }

#pragma unroll
        for (int k = 0; k < 16; k++) {
            float a[8], b[8];
            *(float4*)&a[0] = *(const float4*)&As[s][k][ty * 8];
            *(float4*)&a[4] = *(const float4*)&As[s][k][ty * 8 + 4];
            *(float4*)&b[0] = *(const float4*)&Bs[s][k][tx * 8];
            *(float4*)&b[4] = *(const float4*)&Bs[s][k][tx * 8 + 4];
#pragma unroll
            for (int i = 0; i < 8; i++)
#pragma unroll
                for (int j = 0; j < 8; j++)
                    acc[i][j] += a[i] * b[j];
        }
    }

    const int crow0 = bm * 128 + ty * 8;
    const int ccol0 = bn * 128 + tx * 8;
    float bb[8];
#pragma unroll
    for (int j = 0; j < 8; j++) bb[j] = bias[ccol0 + j];

#pragma unroll
    for (int i = 0; i < 8; i++) {
        float v[8];
#pragma unroll
        for (int j = 0; j < 8; j++) {
            float x = acc[i][j] + bb[j];
            if (RELU) x = fmaxf(x, 0.f);
            v[j] = x;
        }
        float* cp = C + (size_t)(crow0 + i) * N + ccol0;
        *(float4*)(cp)     = *(float4*)&v[0];
        *(float4*)(cp + 4) = *(float4*)&v[4];
    }
}

// ---------------------------------------------------------------------------
// HMMA bf16x3 GEMM — DECODER (math bitwise = R7's proven decoder).
// STAGES=2 -> 80KB smem -> 2 CTAs/SM (the R7 occupancy sweet spot).
// ---------------------------------------------------------------------------
#define TSTRIDE 40
#define SUBTILE (128 * TSTRIDE * 2)      // 10240 B

template <int STAGES, bool RELU, int OMODE>
__global__ __launch_bounds__(256)
void hmma_gemm(const __nv_bfloat16* __restrict__ A0, const __nv_bfloat16* __restrict__ A1,
               const __nv_bfloat16* __restrict__ B0, const __nv_bfloat16* __restrict__ B1,
               const float* __restrict__ bias, float* __restrict__ Cf,
               __nv_bfloat16* __restrict__ C0, __nv_bfloat16* __restrict__ C1,
               int M, int N, int K)
{
    constexpr int STAGE = 4 * SUBTILE;
    extern __shared__ char smem[];
    const uint32_t sbase = smem_u32(smem);

    const int tid  = threadIdx.x;
    const int lane = tid & 31;
    const int wid  = tid >> 5;
    const int wm   = wid & 3;
    const int wn   = wid >> 2;
    const int m0   = blockIdx.y * 128;
    const int n0   = blockIdx.x * 128;
    const int nch  = K >> 5;

    float acc[2][8][4];
#pragma unroll
    for (int a = 0; a < 2; a++)
#pragma unroll
        for (int b = 0; b < 8; b++)
#pragma unroll
            for (int c = 0; c < 4; c++) acc[a][b][c] = 0.f;

    auto load_stage = [&](int stg, int k0) {
        const uint32_t sb_ = sbase + stg * STAGE;
#pragma unroll
        for (int ii = 0; ii < 2; ii++) {
            const int i = tid + ii * 256;
            const int r = i >> 2, c = i & 3;
            const uint32_t so = r * 80 + c * 16;
            const size_t ga = (size_t)(m0 + r) * K + k0 + c * 8;
            const size_t gb = (size_t)(n0 + r) * K + k0 + c * 8;
            cpa16(sb_ + so,               A0 + ga);
            cpa16(sb_ + SUBTILE + so,     A1 + ga);
            cpa16(sb_ + 2 * SUBTILE + so, B0 + gb);
            cpa16(sb_ + 3 * SUBTILE + so, B1 + gb);
        }
    };

#pragma unroll
    for (int s = 0; s < STAGES; s++) {
        if (s < nch) load_stage(s, s * 32);
        CP_COMMIT();
    }

    const int lrow = lane & 15;
    const int lsel = (lane >> 4) << 3;

    for (int ch = 0; ch < nch; ch++) {
        asm volatile("cp.async.wait_group %0;" :: "n"(STAGES - 1) : "memory");
        __syncthreads();
        const uint32_t sb = sbase + (ch % STAGES) * STAGE;
        const uint32_t Ahb = sb, Alb = sb + SUBTILE;
        const uint32_t Bhb = sb + 2 * SUBTILE, Blb = sb + 3 * SUBTILE;

#pragma unroll
        for (int kk = 0; kk < 32; kk += 16) {
            uint32_t ah[2][4], al[2][4];
#pragma unroll
            for (int mt = 0; mt < 2; mt++) {
                uint32_t off = ((wm * 32 + mt * 16 + lrow) * TSTRIDE + kk + lsel) * 2;
                LDSM4(ah[mt][0], ah[mt][1], ah[mt][2], ah[mt][3], Ahb + off);
                LDSM4(al[mt][0], al[mt][1], al[mt][2], al[mt][3], Alb + off);
            }
            uint32_t bh[8][2], bl[8][2];
#pragma unroll
            for (int g = 0; g < 4; g++) {
                uint32_t off = ((wn * 64 + g * 16 + lrow) * TSTRIDE + kk + lsel) * 2;
                uint32_t t0, t1, t2, t3;
                LDSM4(t0, t1, t2, t3, Bhb + off);
                bh[2*g][0] = t0;   bh[2*g][1] = t2;
                bh[2*g+1][0] = t1; bh[2*g+1][1] = t3;
                LDSM4(t0, t1, t2, t3, Blb + off);
                bl[2*g][0] = t0;   bl[2*g][1] = t2;
                bl[2*g+1][0] = t1; bl[2*g+1][1] = t3;
            }
#pragma unroll
            for (int mt = 0; mt < 2; mt++)
#pragma unroll
                for (int nt = 0; nt < 8; nt++) {
                    MMA16816(acc[mt][nt], ah[mt], bh[nt][0], bh[nt][1]);
                    MMA16816(acc[mt][nt], ah[mt], bl[nt][0], bl[nt][1]);
                    MMA16816(acc[mt][nt], al[mt], bh[nt][0], bh[nt][1]);
                }
        }
        __syncthreads();
        if (ch + STAGES < nch) load_stage(ch % STAGES, (ch + STAGES) * 32);
        CP_COMMIT();
    }

    // ---- epilogue ----
    const int gid = lane >> 2;
    const int tg  = lane & 3;
#pragma unroll
    for (int mt = 0; mt < 2; mt++) {
#pragma unroll
        for (int nt = 0; nt < 8; nt++) {
            const int col = n0 + wn * 64 + nt * 8 + tg * 2;
            const float2 bb = __ldg((const float2*)(bias + col));
#pragma unroll
            for (int h = 0; h < 2; h++) {
                const int row = m0 + wm * 32 + mt * 16 + gid + h * 8;
                float v0 = acc[mt][nt][2*h]   + bb.x;
                float v1 = acc[mt][nt][2*h+1] + bb.y;
                if (RELU) { v0 = fmaxf(v0, 0.f); v1 = fmaxf(v1, 0.f); }
                if (OMODE == 0) {
                    *(float2*)(Cf + (size_t)row * N + col) = make_float2(v0, v1);
                } else {
                    __nv_bfloat16 h0 = __float2bfloat16(v0);
                    __nv_bfloat16 h1 = __float2bfloat16(v1);
                    __nv_bfloat162 p0; p0.x = h0; p0.y = h1;
                    __nv_bfloat162 p1;
                    p1.x = __float2bfloat16(v0 - __bfloat162float(h0));
                    p1.y = __float2bfloat16(v1 - __bfloat162float(h1));
                    *(__nv_bfloat162*)(C0 + (size_t)row * N + col) = p0;
                    *(__nv_bfloat162*)(C1 + (size_t)row * N + col) = p1;
                }
            }
        }
    }
}

// ---------------------------------------------------------------------------
// Preprocessing: weight transpose + bf16 split
// ---------------------------------------------------------------------------
__global__ void k_wprep2(const float* __restrict__ W, __nv_bfloat16* __restrict__ T0,
                         __nv_bfloat16* __restrict__ T1, int K, int N)
{
    __shared__ float t[32][33];
    int n = blockIdx.x * 32 + threadIdx.x;
    int k = blockIdx.y * 32 + threadIdx.y;
    t[threadIdx.y][threadIdx.x] = W[(size_t)k * N + n];
    __syncthreads();
    int nn = blockIdx.x * 32 + threadIdx.y;
    int kk = blockIdx.y * 32 + threadIdx.x;
    float v = t[threadIdx.x][threadIdx.y];
    __nv_bfloat16 h = __float2bfloat16(v);
    T0[(size_t)nn * K + kk] = h;
    T1[(size_t)nn * K + kk] = __float2bfloat16(v - __bfloat162float(h));
}

// fused: write x_q output + bf16 hi/lo split for the decoder, one xq read
__global__ void k_xq_out(const float* __restrict__ xq, float* __restrict__ dst,
                         __nv_bfloat16* __restrict__ o0, __nv_bfloat16* __restrict__ o1)
{
    int i = blockIdx.x * 256 + threadIdx.x;
    if (i < BROWS * ZD) {
        float v = xq[i];
        dst[i] = v;
        __nv_bfloat16 h = __float2bfloat16(v);
        o0[i] = h;
        o1[i] = __float2bfloat16(v - __bfloat162float(h));
    }
}

// ---------------------------------------------------------------------------
// Expert counting-sort
// ---------------------------------------------------------------------------
__global__ void k_zero_counts() {
    int t = threadIdx.x;
    if (t < NUM_EXPERTS) { g_counts[t] = 0; g_cursor[t] = 0; }
}
__global__ void k_hist(const int* __restrict__ labels) {
    int i = blockIdx.x * blockDim.x + threadIdx.x;
    if (i < BROWS) atomicAdd(&g_counts[labels[i]], 1);
}
__global__ void k_scan() {
    if (threadIdx.x == 0) {
        int s = 0;
        for (int e = 0; e < NUM_EXPERTS; e++) { g_offsets[e] = s; s += g_counts[e]; }
        g_offsets[NUM_EXPERTS] = s;
    }
}
__global__ void k_scatter(const int* __restrict__ labels) {
    int i = blockIdx.x * blockDim.x + threadIdx.x;
    if (i < BROWS) {
        int e = labels[i];
        int p = atomicAdd(&g_cursor[e], 1);
        g_perm[g_offsets[e] + p] = i;
    }
}
__global__ void k_rq_init() {
    int i = blockIdx.x * blockDim.x + threadIdx.x;
    if (i < BROWS * ZD) g_xq[i] = 0.f;
    if (i < BROWS)      g_lossbuf[i] = 0.f;
}

// ---------------------------------------------------------------------------
// Residual quantization (validated round 1)
// ---------------------------------------------------------------------------
__global__ void rq_level(const float* __restrict__ cb,
                         float* __restrict__ idx_out, int level)
{
    extern __shared__ float c_sh[];        // 256 * 129 floats
    __shared__ float res_sh[ZD];
    __shared__ float cn_sh[CBK];
    __shared__ float s_sc[CBK];
    __shared__ int   s_ix[CBK];
    __shared__ float s_red[4];
    __shared__ int   s_kmin;

    const int e     = blockIdx.y;
    const int start = g_offsets[e];
    const int end   = g_offsets[e + 1];
    const int rbase = start + blockIdx.x * 32;
    if (rbase >= end) return;

    const int t = threadIdx.x;
    const float* cbl = cb + ((size_t)level * NUM_EXPERTS + e) * CBK * ZD;
    for (int i = t; i < (CBK * ZD) / 4; i += 256) {
        float4 v = ((const float4*)cbl)[i];
        int k = i >> 5;
        int j = (i & 31) << 2;
        float* d = &c_sh[k * 129 + j];
        d[0] = v.x; d[1] = v.y; d[2] = v.z; d[3] = v.w;
    }
    __syncthreads();

    {
        const float* cr = &c_sh[t * 129];
        float s = 0.f;
#pragma unroll 8
        for (int j = 0; j < ZD; j++) s += cr[j] * cr[j];
        cn_sh[t] = s;
    }
    __syncthreads();

    const int nrows = min(32, end - rbase);
    for (int i = 0; i < nrows; i++) {
        const int row = g_perm[rbase + i];
        if (t < ZD) res_sh[t] = g_res[row * ZD + t];
        __syncthreads();

        float dot = 0.f;
        const float* cr = &c_sh[t * 129];
#pragma unroll 8
        for (int j = 0; j < ZD; j++) dot += cr[j] * res_sh[j];
        s_sc[t] = cn_sh[t] - 2.f * dot;
        s_ix[t] = t;
        __syncthreads();

#pragma unroll
        for (int s = 128; s > 0; s >>= 1) {
            if (t < s) {
                float sc2 = s_sc[t + s]; int ix2 = s_ix[t + s];
                if (sc2 < s_sc[t] || (sc2 == s_sc[t] && ix2 < s_ix[t])) {
                    s_sc[t] = sc2; s_ix[t] = ix2;
                }
            }
            __syncthreads();
        }
        if (t == 0) s_kmin = s_ix[0];
        __syncthreads();
        const int kmin = s_kmin;

        float sq = 0.f;
        if (t < ZD) {
            float q  = c_sh[kmin * 129 + t];
            float nr = res_sh[t] - q;
            g_res[row * ZD + t] = nr;
            g_xq [row * ZD + t] += q;
            sq = nr * nr;
        }
#pragma unroll
        for (int o = 16; o > 0; o >>= 1) sq += __shfl_down_sync(0xffffffffu, sq, o);
        if (t < ZD && (t & 31) == 0) s_red[t >> 5] = sq;
        __syncthreads();
        if (t == 0) {
            g_lossbuf[row] += s_red[0] + s_red[1] + s_red[2] + s_red[3];
            idx_out[row * 4 + level] = (float)kmin;
        }
        __syncthreads();
    }
}

__global__ void k_loss_finish(float* __restrict__ loss_out) {
    __shared__ float sm[1024];
    float s = 0.f;
    for (int i = threadIdx.x; i < BROWS; i += 1024) s += g_lossbuf[i];
    sm[threadIdx.x] = s;
    __syncthreads();
    for (int k = 512; k > 0; k >>= 1) {
        if (threadIdx.x < k) sm[threadIdx.x] += sm[threadIdx.x + k];
        __syncthreads();
    }
    if (threadIdx.x == 0)
        loss_out[0] = sm[0] * (1.f + BETA) / ((float)BROWS * (float)ZD);
}

// ---------------------------------------------------------------------------
// Host launch
// ---------------------------------------------------------------------------
template <bool RELU>
static void launch_sgemm(const float* A, const float* W, const float* b, float* C,
                         int M, int N, int K)
{
    dim3 grid(N / 128, M / 128);
    sgemm_db<RELU><<<grid, 256>>>(A, W, b, C, M, N, K);
}

template <int STAGES, bool RELU, int OMODE>
static void launch_hmma(const __nv_bfloat16* a0, const __nv_bfloat16* a1,
                        const __nv_bfloat16* b0, const __nv_bfloat16* b1,
                        const float* bias, float* cf,
                        __nv_bfloat16* c0, __nv_bfloat16* c1,
                        int M, int N, int K)
{
    constexpr int SMEMB = STAGES * 4 * SUBTILE;
    cudaFuncSetAttribute(hmma_gemm<STAGES, RELU, OMODE>,
                         cudaFuncAttributeMaxDynamicSharedMemorySize, SMEMB);
    dim3 g(N / 128, M / 128);
    hmma_gemm<STAGES, RELU, OMODE><<<g, 256, SMEMB>>>(
        a0, a1, b0, b1, bias, cf, c0, c1, M, N, K);
}

extern "C" void kernel_launch(void* const* d_in, const int* in_sizes, int n_in,
                              void* d_out, int out_size)
{
    const float* x      = (const float*)d_in[0];
    const int*   labels = (const int*)  d_in[1];
    const float* ew[4]  = {(const float*)d_in[2], (const float*)d_in[4],
                           (const float*)d_in[6], (const float*)d_in[8]};
    const float* eb[4]  = {(const float*)d_in[3], (const float*)d_in[5],
                           (const float*)d_in[7], (const float*)d_in[9]};
    const float* dw[4]  = {(const float*)d_in[10], (const float*)d_in[12],
                           (const float*)d_in[14], (const float*)d_in[16]};
    const float* db[4]  = {(const float*)d_in[11], (const float*)d_in[13],
                           (const float*)d_in[15], (const float*)d_in[17]};
    const float* cb     = (const float*)d_in[18];
    float* out = (float*)d_out;

    float *buf0, *buf1, *res, *xq;
    __nv_bfloat16 *dA0, *dA1, *dB0, *dB1, *dw0, *dw1;
    cudaGetSymbolAddress((void**)&buf0, g_buf0);
    cudaGetSymbolAddress((void**)&buf1, g_buf1);
    cudaGetSymbolAddress((void**)&res,  g_res);
    cudaGetSymbolAddress((void**)&xq,   g_xq);
    cudaGetSymbolAddress((void**)&dA0,  g_dA0);
    cudaGetSymbolAddress((void**)&dA1,  g_dA1);
    cudaGetSymbolAddress((void**)&dB0,  g_dB0);
    cudaGetSymbolAddress((void**)&dB1,  g_dB1);
    cudaGetSymbolAddress((void**)&dw0,  g_dw0);
    cudaGetSymbolAddress((void**)&dw1,  g_dw1);

    static const int RQ_SMEM = CBK * 129 * sizeof(float);
    cudaFuncSetAttribute(rq_level, cudaFuncAttributeMaxDynamicSharedMemorySize, RQ_SMEM);

    // decoder weight table ([N,K] after transpose)
    const int dLN[4] = {512, 1024, 2048, 768};
    const int dLK[4] = {128, 512, 1024, 2048};
    size_t doff[4];
    {
        size_t o = 0;
        for (int i = 0; i < 4; i++) { doff[i] = o; o += (size_t)dLN[i] * dLK[i]; }
    }

    // ---- preprocess decoder weights ----
    for (int i = 0; i < 4; i++) {
        dim3 gd(dLN[i] / 32, dLK[i] / 32), b(32, 32);
        k_wprep2<<<gd, b>>>(dw[i], dw0 + doff[i], dw1 + doff[i], dLK[i], dLN[i]);
    }

    // ---- expert grouping ----
    k_zero_counts<<<1, 32>>>();
    k_hist   <<<BROWS / 256, 256>>>(labels);
    k_scan   <<<1, 1>>>();
    k_scatter<<<BROWS / 256, 256>>>(labels);

    // ---- encoder (fp32 SIMT v2 — bitwise-identical z to round 1) ----
    launch_sgemm<true >(x,    ew[0], eb[0], buf0, BROWS, 2048, 768);
    launch_sgemm<true >(buf0, ew[1], eb[1], buf1, BROWS, 1024, 2048);
    launch_sgemm<true >(buf1, ew[2], eb[2], buf0, BROWS, 512,  1024);
    launch_sgemm<false>(buf0, ew[3], eb[3], res,  BROWS, 128,  512);

    // ---- residual quantization ----
    k_rq_init<<<(BROWS * ZD + 255) / 256, 256>>>();
    dim3 rqg((BROWS + 31) / 32, NUM_EXPERTS);
    for (int l = 0; l < NUM_LEVELS; l++)
        rq_level<<<rqg, 256, RQ_SMEM>>>(cb, out + IDX_OFF, l);
    k_loss_finish<<<1, 1024>>>(out + LOSS_OFF);

    // ---- x_q output + decoder input split (fused) ----
    k_xq_out<<<(BROWS * ZD + 255) / 256, 256>>>(xq, out + XQ_OFF, dA0, dA1);

    // ---- decoder (bf16x3 HMMA, STAGES=2 -> 2 CTAs/SM) ----
    launch_hmma<2, true, 1>(dA0, dA1, dw0 + doff[0], dw1 + doff[0], db[0],
                            nullptr, dB0, dB1, BROWS, 512, 128);
    launch_hmma<2, true, 1>(dB0, dB1, dw0 + doff[1], dw1 + doff[1], db[1],
                            nullptr, dA0, dA1, BROWS, 1024, 512);
    launch_hmma<2, true, 1>(dA0, dA1, dw0 + doff[2], dw1 + doff[2], db[2],
                            nullptr, dB0, dB1, BROWS, 2048, 1024);
    launch_hmma<2, false, 0>(dB0, dB1, dw0 + doff[3], dw1 + doff[3], db[3],
                             out + OUT_OFF, nullptr, nullptr, BROWS, 768, 2048);
}

// round 11
// speedup vs baseline: 1.1105x; 1.0698x over previous
#include <cuda_runtime.h>
#include <cuda_bf16.h>
#include <cstdint>

// ---------------------------------------------------------------------------
// Problem constants
// ---------------------------------------------------------------------------
#define BROWS 32768
#define NUM_EXPERTS 10
#define NUM_LEVELS 4
#define CBK 256
#define ZD 128
#define BETA 0.001f

// Output layout (float32, tuple flattened: out, loss, indices, x_q)
#define OUT_OFF  0
#define LOSS_OFF (32768 * 768)
#define IDX_OFF  (LOSS_OFF + 1)
#define XQ_OFF   (IDX_OFF + 32768 * 4)

// ---------------------------------------------------------------------------
// Device scratch
// ---------------------------------------------------------------------------
__device__ float g_buf0[32768u * 2048u];   // encoder ping
__device__ float g_buf1[32768u * 1024u];   // encoder pong
__device__ float g_res [32768 * ZD];
__device__ float g_xq  [32768 * ZD];
__device__ float g_lossbuf[32768];
__device__ int   g_counts[NUM_EXPERTS];
__device__ int   g_cursor[NUM_EXPERTS];
__device__ int   g_offsets[NUM_EXPERTS + 1];
__device__ int   g_perm[32768];

// decoder bf16 hi/lo activation ping-pong + pre-split transposed weights
__device__ __nv_bfloat16 g_dA0[32768u * 1024u];
__device__ __nv_bfloat16 g_dA1[32768u * 1024u];
__device__ __nv_bfloat16 g_dB0[32768u * 2048u];
__device__ __nv_bfloat16 g_dB1[32768u * 2048u];
#define W_TOTAL 4259840
__device__ __nv_bfloat16 g_dw0[W_TOTAL];
__device__ __nv_bfloat16 g_dw1[W_TOTAL];

// ---------------------------------------------------------------------------
// PTX helpers
// ---------------------------------------------------------------------------
__device__ __forceinline__ uint32_t smem_u32(const void* p) {
    uint32_t a;
    asm("{ .reg .u64 t; cvta.to.shared.u64 t, %1; cvt.u32.u64 %0, t; }"
        : "=r"(a) : "l"(p));
    return a;
}
__device__ __forceinline__ void cpa16(uint32_t dst, const void* src) {
    asm volatile("cp.async.cg.shared.global [%0], [%1], 16;" :: "r"(dst), "l"(src) : "memory");
}
#define CP_COMMIT() asm volatile("cp.async.commit_group;" ::: "memory")

#define LDSM4(r0, r1, r2, r3, addr) \
    asm volatile("ldmatrix.sync.aligned.m8n8.x4.shared.b16 {%0,%1,%2,%3}, [%4];" \
        : "=r"(r0), "=r"(r1), "=r"(r2), "=r"(r3) : "r"(addr))

#define MMA16816(acc, a, b0, b1) \
    asm volatile("mma.sync.aligned.m16n8k16.row.col.f32.bf16.bf16.f32 " \
        "{%0,%1,%2,%3}, {%4,%5,%6,%7}, {%8,%9}, {%0,%1,%2,%3};" \
        : "+f"((acc)[0]), "+f"((acc)[1]), "+f"((acc)[2]), "+f"((acc)[3]) \
        : "r"((a)[0]), "r"((a)[1]), "r"((a)[2]), "r"((a)[3]), "r"(b0), "r"(b1))

// packed fp32 FMA (sm_103a dual-rate path; per-lane IEEE fma.rn)
#define FMA2(d, a, b) \
    asm("fma.rn.f32x2 %0, %1, %2, %0;" : "+l"(d) : "l"(a), "l"(b))
#define PACK2(out, x) \
    asm("mov.b64 %0, {%1, %1};" : "=l"(out) : "f"(x))
#define UNPACK2(lo, hi, in) \
    asm("mov.b64 {%0, %1}, %2;" : "=f"(lo), "=f"(hi) : "l"(in))

// ---------------------------------------------------------------------------
// fp32 SIMT SGEMM v3 — ENCODER. Same FMA set & per-element accumulation order
// as rounds 1/9/10, but executed as packed fma.rn.f32x2 (FFMA2): each packed
// op performs two independent IEEE fp32 FMAs -> bitwise-identical z.
// ---------------------------------------------------------------------------
template <bool RELU>
__global__ __launch_bounds__(256, 2)
void sgemm_db(const float* __restrict__ A, const float* __restrict__ W,
              const float* __restrict__ bias, float* __restrict__ C,
              int M, int N, int K)
{
    __shared__ float As[2][16][128];   // [stage][k][row]
    __shared__ float Bs[2][16][128];   // [stage][k][col]

    const int t  = threadIdx.x;
    const int bm = blockIdx.y;
    const int bn = blockIdx.x;
    const int tx = t & 15;
    const int ty = t >> 4;

    const int ar0 = t >> 2;            // 0..63
    const int akq = (t & 3) * 4;       // 0,4,8,12
    const int bk0 = t >> 5;            // 0..7
    const int bcq = (t & 31) * 4;      // 0..124

    const float* Ag = A + (size_t)(bm * 128) * K;
    const float* Wg = W + bn * 128;

    unsigned long long acc2[8][4];     // [i][j-pair]; lanes = cols (2j, 2j+1)
#pragma unroll
    for (int i = 0; i < 8; i++)
#pragma unroll
        for (int j = 0; j < 4; j++) acc2[i][j] = 0ull;

    const int nch = K >> 4;

    float4 pa0 = *(const float4*)(Ag + (size_t)ar0 * K + akq);
    float4 pa1 = *(const float4*)(Ag + (size_t)(64 + ar0) * K + akq);
    float4 pb0 = *(const float4*)(Wg + (size_t)bk0 * N + bcq);
    float4 pb1 = *(const float4*)(Wg + (size_t)(8 + bk0) * N + bcq);

    for (int ch = 0; ch < nch; ch++) {
        const int s = ch & 1;
        As[s][akq + 0][ar0] = pa0.x;
        As[s][akq + 1][ar0] = pa0.y;
        As[s][akq + 2][ar0] = pa0.z;
        As[s][akq + 3][ar0] = pa0.w;
        As[s][akq + 0][64 + ar0] = pa1.x;
        As[s][akq + 1][64 + ar0] = pa1.y;
        As[s][akq + 2][64 + ar0] = pa1.z;
        As[s][akq + 3][64 + ar0] = pa1.w;
        *(float4*)&Bs[s][bk0][bcq]     = pb0;
        *(float4*)&Bs[s][8 + bk0][bcq] = pb1;
        __syncthreads();

        if (ch + 1 < nch) {
            const int k0 = (ch + 1) << 4;
            pa0 = *(const float4*)(Ag + (size_t)ar0 * K + k0 + akq);
            pa1 = *(const float4*)(Ag + (size_t)(64 + ar0) * K + k0 + akq);
            pb0 = *(const float4*)(Wg + (size_t)(k0 + bk0) * N + bcq);
            pb1 = *(const float4*)(Wg + (size_t)(k0 + 8 + bk0) * N + bcq);
        }

#pragma unroll
        for (int k = 0; k < 16; k++) {
            float a[8];
            *(float4*)&a[0] = *(const float4*)&As[s][k][ty * 8];
            *(float4*)&a[4] = *(const float4*)&As[s][k][ty * 8 + 4];
            // b pairs read directly as packed 64-bit lanes (lo = lower col)
            const ulonglong2 b01 = *(const ulonglong2*)&Bs[s][k][tx * 8];
            const ulonglong2 b23 = *(const ulonglong2*)&Bs[s][k][tx * 8 + 4];
            unsigned long long bp[4] = {b01.x, b01.y, b23.x, b23.y};
            unsigned long long ap[8];
#pragma unroll
            for (int i = 0; i < 8; i++) PACK2(ap[i], a[i]);
#pragma unroll
            for (int i = 0; i < 8; i++)
#pragma unroll
                for (int j = 0; j < 4; j++)
                    FMA2(acc2[i][j], ap[i], bp[j]);
        }
    }

    const int crow0 = bm * 128 + ty * 8;
    const int ccol0 = bn * 128 + tx * 8;
    float bb[8];
#pragma unroll
    for (int j = 0; j < 8; j++) bb[j] = bias[ccol0 + j];

#pragma unroll
    for (int i = 0; i < 8; i++) {
        float v[8];
#pragma unroll
        for (int j = 0; j < 4; j++) {
            float lo, hi;
            UNPACK2(lo, hi, acc2[i][j]);
            float x0 = lo + bb[2 * j];
            float x1 = hi + bb[2 * j + 1];
            if (RELU) { x0 = fmaxf(x0, 0.f); x1 = fmaxf(x1, 0.f); }
            v[2 * j] = x0;
            v[2 * j + 1] = x1;
        }
        float* cp = C + (size_t)(crow0 + i) * N + ccol0;
        *(float4*)(cp)     = *(float4*)&v[0];
        *(float4*)(cp + 4) = *(float4*)&v[4];
    }
}

// ---------------------------------------------------------------------------
// HMMA bf16x3 GEMM — DECODER (unchanged from R10: STAGES=2, 2 CTAs/SM).
// ---------------------------------------------------------------------------
#define TSTRIDE 40
#define SUBTILE (128 * TSTRIDE * 2)      // 10240 B

template <int STAGES, bool RELU, int OMODE>
__global__ __launch_bounds__(256)
void hmma_gemm(const __nv_bfloat16* __restrict__ A0, const __nv_bfloat16* __restrict__ A1,
               const __nv_bfloat16* __restrict__ B0, const __nv_bfloat16* __restrict__ B1,
               const float* __restrict__ bias, float* __restrict__ Cf,
               __nv_bfloat16* __restrict__ C0, __nv_bfloat16* __restrict__ C1,
               int M, int N, int K)
{
    constexpr int STAGE = 4 * SUBTILE;
    extern __shared__ char smem[];
    const uint32_t sbase = smem_u32(smem);

    const int tid  = threadIdx.x;
    const int lane = tid & 31;
    const int wid  = tid >> 5;
    const int wm   = wid & 3;
    const int wn   = wid >> 2;
    const int m0   = blockIdx.y * 128;
    const int n0   = blockIdx.x * 128;
    const int nch  = K >> 5;

    float acc[2][8][4];
#pragma unroll
    for (int a = 0; a < 2; a++)
#pragma unroll
        for (int b = 0; b < 8; b++)
#pragma unroll
            for (int c = 0; c < 4; c++) acc[a][b][c] = 0.f;

    auto load_stage = [&](int stg, int k0) {
        const uint32_t sb_ = sbase + stg * STAGE;
#pragma unroll
        for (int ii = 0; ii < 2; ii++) {
            const int i = tid + ii * 256;
            const int r = i >> 2, c = i & 3;
            const uint32_t so = r * 80 + c * 16;
            const size_t ga = (size_t)(m0 + r) * K + k0 + c * 8;
            const size_t gb = (size_t)(n0 + r) * K + k0 + c * 8;
            cpa16(sb_ + so,               A0 + ga);
            cpa16(sb_ + SUBTILE + so,     A1 + ga);
            cpa16(sb_ + 2 * SUBTILE + so, B0 + gb);
            cpa16(sb_ + 3 * SUBTILE + so, B1 + gb);
        }
    };

#pragma unroll
    for (int s = 0; s < STAGES; s++) {
        if (s < nch) load_stage(s, s * 32);
        CP_COMMIT();
    }

    const int lrow = lane & 15;
    const int lsel = (lane >> 4) << 3;

    for (int ch = 0; ch < nch; ch++) {
        asm volatile("cp.async.wait_group %0;" :: "n"(STAGES - 1) : "memory");
        __syncthreads();
        const uint32_t sb = sbase + (ch % STAGES) * STAGE;
        const uint32_t Ahb = sb, Alb = sb + SUBTILE;
        const uint32_t Bhb = sb + 2 * SUBTILE, Blb = sb + 3 * SUBTILE;

#pragma unroll
        for (int kk = 0; kk < 32; kk += 16) {
            uint32_t ah[2][4], al[2][4];
#pragma unroll
            for (int mt = 0; mt < 2; mt++) {
                uint32_t off = ((wm * 32 + mt * 16 + lrow) * TSTRIDE + kk + lsel) * 2;
                LDSM4(ah[mt][0], ah[mt][1], ah[mt][2], ah[mt][3], Ahb + off);
                LDSM4(al[mt][0], al[mt][1], al[mt][2], al[mt][3], Alb + off);
            }
            uint32_t bh[8][2], bl[8][2];
#pragma unroll
            for (int g = 0; g < 4; g++) {
                uint32_t off = ((wn * 64 + g * 16 + lrow) * TSTRIDE + kk + lsel) * 2;
                uint32_t t0, t1, t2, t3;
                LDSM4(t0, t1, t2, t3, Bhb + off);
                bh[2*g][0] = t0;   bh[2*g][1] = t2;
                bh[2*g+1][0] = t1; bh[2*g+1][1] = t3;
                LDSM4(t0, t1, t2, t3, Blb + off);
                bl[2*g][0] = t0;   bl[2*g][1] = t2;
                bl[2*g+1][0] = t1; bl[2*g+1][1] = t3;
            }
#pragma unroll
            for (int mt = 0; mt < 2; mt++)
#pragma unroll
                for (int nt = 0; nt < 8; nt++) {
                    MMA16816(acc[mt][nt], ah[mt], bh[nt][0], bh[nt][1]);
                    MMA16816(acc[mt][nt], ah[mt], bl[nt][0], bl[nt][1]);
                    MMA16816(acc[mt][nt], al[mt], bh[nt][0], bh[nt][1]);
                }
        }
        __syncthreads();
        if (ch + STAGES < nch) load_stage(ch % STAGES, (ch + STAGES) * 32);
        CP_COMMIT();
    }

    // ---- epilogue ----
    const int gid = lane >> 2;
    const int tg  = lane & 3;
#pragma unroll
    for (int mt = 0; mt < 2; mt++) {
#pragma unroll
        for (int nt = 0; nt < 8; nt++) {
            const int col = n0 + wn * 64 + nt * 8 + tg * 2;
            const float2 bb = __ldg((const float2*)(bias + col));
#pragma unroll
            for (int h = 0; h < 2; h++) {
                const int row = m0 + wm * 32 + mt * 16 + gid + h * 8;
                float v0 = acc[mt][nt][2*h]   + bb.x;
                float v1 = acc[mt][nt][2*h+1] + bb.y;
                if (RELU) { v0 = fmaxf(v0, 0.f); v1 = fmaxf(v1, 0.f); }
                if (OMODE == 0) {
                    *(float2*)(Cf + (size_t)row * N + col) = make_float2(v0, v1);
                } else {
                    __nv_bfloat16 h0 = __float2bfloat16(v0);
                    __nv_bfloat16 h1 = __float2bfloat16(v1);
                    __nv_bfloat162 p0; p0.x = h0; p0.y = h1;
                    __nv_bfloat162 p1;
                    p1.x = __float2bfloat16(v0 - __bfloat162float(h0));
                    p1.y = __float2bfloat16(v1 - __bfloat162float(h1));
                    *(__nv_bfloat162*)(C0 + (size_t)row * N + col) = p0;
                    *(__nv_bfloat162*)(C1 + (size_t)row * N + col) = p1;
                }
            }
        }
    }
}

// ---------------------------------------------------------------------------
// Preprocessing: weight transpose + bf16 split; fused xq output/split
// ---------------------------------------------------------------------------
__global__ void k_wprep2(const float* __restrict__ W, __nv_bfloat16* __restrict__ T0,
                         __nv_bfloat16* __restrict__ T1, int K, int N)
{
    __shared__ float t[32][33];
    int n = blockIdx.x * 32 + threadIdx.x;
    int k = blockIdx.y * 32 + threadIdx.y;
    t[threadIdx.y][threadIdx.x] = W[(size_t)k * N + n];
    __syncthreads();
    int nn = blockIdx.x * 32 + threadIdx.y;
    int kk = blockIdx.y * 32 + threadIdx.x;
    float v = t[threadIdx.x][threadIdx.y];
    __nv_bfloat16 h = __float2bfloat16(v);
    T0[(size_t)nn * K + kk] = h;
    T1[(size_t)nn * K + kk] = __float2bfloat16(v - __bfloat162float(h));
}

__global__ void k_xq_out(const float* __restrict__ xq, float* __restrict__ dst,
                         __nv_bfloat16* __restrict__ o0, __nv_bfloat16* __restrict__ o1)
{
    int i = blockIdx.x * 256 + threadIdx.x;
    if (i < BROWS * ZD) {
        float v = xq[i];
        dst[i] = v;
        __nv_bfloat16 h = __float2bfloat16(v);
        o0[i] = h;
        o1[i] = __float2bfloat16(v - __bfloat162float(h));
    }
}

// ---------------------------------------------------------------------------
// Expert counting-sort
// ---------------------------------------------------------------------------
__global__ void k_zero_counts() {
    int t = threadIdx.x;
    if (t < NUM_EXPERTS) { g_counts[t] = 0; g_cursor[t] = 0; }
}
__global__ void k_hist(const int* __restrict__ labels) {
    int i = blockIdx.x * blockDim.x + threadIdx.x;
    if (i < BROWS) atomicAdd(&g_counts[labels[i]], 1);
}
__global__ void k_scan() {
    if (threadIdx.x == 0) {
        int s = 0;
        for (int e = 0; e < NUM_EXPERTS; e++) { g_offsets[e] = s; s += g_counts[e]; }
        g_offsets[NUM_EXPERTS] = s;
    }
}
__global__ void k_scatter(const int* __restrict__ labels) {
    int i = blockIdx.x * blockDim.x + threadIdx.x;
    if (i < BROWS) {
        int e = labels[i];
        int p = atomicAdd(&g_cursor[e], 1);
        g_perm[g_offsets[e] + p] = i;
    }
}
__global__ void k_rq_init() {
    int i = blockIdx.x * blockDim.x + threadIdx.x;
    if (i < BROWS * ZD) g_xq[i] = 0.f;
    if (i < BROWS)      g_lossbuf[i] = 0.f;
}

// ---------------------------------------------------------------------------
// Residual quantization — warp-shuffle argmin (lexicographic (score,index)
// min is a unique total-order selection: any reduction order gives the same
// index as the round-1 tree).
// ---------------------------------------------------------------------------
__global__ void rq_level(const float* __restrict__ cb,
                         float* __restrict__ idx_out, int level)
{
    extern __shared__ float c_sh[];        // 256 * 129 floats
    __shared__ float res_sh[ZD];
    __shared__ float cn_sh[CBK];
    __shared__ float s_ws[8];
    __shared__ int   s_wi[8];
    __shared__ float s_red[4];
    __shared__ int   s_kmin;

    const int e     = blockIdx.y;
    const int start = g_offsets[e];
    const int end   = g_offsets[e + 1];
    const int rbase = start + blockIdx.x * 32;
    if (rbase >= end) return;

    const int t = threadIdx.x;
    const int lane = t & 31;
    const int warp = t >> 5;

    const float* cbl = cb + ((size_t)level * NUM_EXPERTS + e) * CBK * ZD;
    for (int i = t; i < (CBK * ZD) / 4; i += 256) {
        float4 v = ((const float4*)cbl)[i];
        int k = i >> 5;
        int j = (i & 31) << 2;
        float* d = &c_sh[k * 129 + j];
        d[0] = v.x; d[1] = v.y; d[2] = v.z; d[3] = v.w;
    }
    __syncthreads();

    {
        const float* cr = &c_sh[t * 129];
        float s = 0.f;
#pragma unroll 8
        for (int j = 0; j < ZD; j++) s += cr[j] * cr[j];
        cn_sh[t] = s;
    }
    __syncthreads();

    const int nrows = min(32, end - rbase);
    for (int i = 0; i < nrows; i++) {
        const int row = g_perm[rbase + i];
        if (t < ZD) res_sh[t] = g_res[row * ZD + t];
        __syncthreads();

        float dot = 0.f;
        const float* cr = &c_sh[t * 129];
#pragma unroll 8
        for (int j = 0; j < ZD; j++) dot += cr[j] * res_sh[j];
        float sc = cn_sh[t] - 2.f * dot;
        int   ix = t;

        // warp-level lexicographic min
#pragma unroll
        for (int o = 16; o > 0; o >>= 1) {
            float sc2 = __shfl_down_sync(0xffffffffu, sc, o);
            int   ix2 = __shfl_down_sync(0xffffffffu, ix, o);
            if (sc2 < sc || (sc2 == sc && ix2 < ix)) { sc = sc2; ix = ix2; }
        }
        if (lane == 0) { s_ws[warp] = sc; s_wi[warp] = ix; }
        __syncthreads();
        if (t == 0) {
            float bs = s_ws[0]; int bi = s_wi[0];
#pragma unroll
            for (int w = 1; w < 8; w++) {
                float s2 = s_ws[w]; int i2 = s_wi[w];
                if (s2 < bs || (s2 == bs && i2 < bi)) { bs = s2; bi = i2; }
            }
            s_kmin = bi;
        }
        __syncthreads();
        const int kmin = s_kmin;

        float sq = 0.f;
        if (t < ZD) {
            float q  = c_sh[kmin * 129 + t];
            float nr = res_sh[t] - q;
            g_res[row * ZD + t] = nr;
            g_xq [row * ZD + t] += q;
            sq = nr * nr;
        }
#pragma unroll
        for (int o = 16; o > 0; o >>= 1) sq += __shfl_down_sync(0xffffffffu, sq, o);
        if (t < ZD && lane == 0) s_red[warp] = sq;
        __syncthreads();
        if (t == 0) {
            g_lossbuf[row] += s_red[0] + s_red[1] + s_red[2] + s_red[3];
            idx_out[row * 4 + level] = (float)kmin;
        }
        __syncthreads();
    }
}

__global__ void k_loss_finish(float* __restrict__ loss_out) {
    __shared__ float sm[1024];
    float s = 0.f;
    for (int i = threadIdx.x; i < BROWS; i += 1024) s += g_lossbuf[i];
    sm[threadIdx.x] = s;
    __syncthreads();
    for (int k = 512; k > 0; k >>= 1) {
        if (threadIdx.x < k) sm[threadIdx.x] += sm[threadIdx.x + k];
        __syncthreads();
    }
    if (threadIdx.x == 0)
        loss_out[0] = sm[0] * (1.f + BETA) / ((float)BROWS * (float)ZD);
}

// ---------------------------------------------------------------------------
// Host launch
// ---------------------------------------------------------------------------
template <bool RELU>
static void launch_sgemm(const float* A, const float* W, const float* b, float* C,
                         int M, int N, int K)
{
    dim3 grid(N / 128, M / 128);
    sgemm_db<RELU><<<grid, 256>>>(A, W, b, C, M, N, K);
}

template <int STAGES, bool RELU, int OMODE>
static void launch_hmma(const __nv_bfloat16* a0, const __nv_bfloat16* a1,
                        const __nv_bfloat16* b0, const __nv_bfloat16* b1,
                        const float* bias, float* cf,
                        __nv_bfloat16* c0, __nv_bfloat16* c1,
                        int M, int N, int K)
{
    constexpr int SMEMB = STAGES * 4 * SUBTILE;
    cudaFuncSetAttribute(hmma_gemm<STAGES, RELU, OMODE>,
                         cudaFuncAttributeMaxDynamicSharedMemorySize, SMEMB);
    dim3 g(N / 128, M / 128);
    hmma_gemm<STAGES, RELU, OMODE><<<g, 256, SMEMB>>>(
        a0, a1, b0, b1, bias, cf, c0, c1, M, N, K);
}

extern "C" void kernel_launch(void* const* d_in, const int* in_sizes, int n_in,
                              void* d_out, int out_size)
{
    const float* x      = (const float*)d_in[0];
    const int*   labels = (const int*)  d_in[1];
    const float* ew[4]  = {(const float*)d_in[2], (const float*)d_in[4],
                           (const float*)d_in[6], (const float*)d_in[8]};
    const float* eb[4]  = {(const float*)d_in[3], (const float*)d_in[5],
                           (const float*)d_in[7], (const float*)d_in[9]};
    const float* dw[4]  = {(const float*)d_in[10], (const float*)d_in[12],
                           (const float*)d_in[14], (const float*)d_in[16]};
    const float* db[4]  = {(const float*)d_in[11], (const float*)d_in[13],
                           (const float*)d_in[15], (const float*)d_in[17]};
    const float* cb     = (const float*)d_in[18];
    float* out = (float*)d_out;

    float *buf0, *buf1, *res, *xq;
    __nv_bfloat16 *dA0, *dA1, *dB0, *dB1, *dw0, *dw1;
    cudaGetSymbolAddress((void**)&buf0, g_buf0);
    cudaGetSymbolAddress((void**)&buf1, g_buf1);
    cudaGetSymbolAddress((void**)&res,  g_res);
    cudaGetSymbolAddress((void**)&xq,   g_xq);
    cudaGetSymbolAddress((void**)&dA0,  g_dA0);
    cudaGetSymbolAddress((void**)&dA1,  g_dA1);
    cudaGetSymbolAddress((void**)&dB0,  g_dB0);
    cudaGetSymbolAddress((void**)&dB1,  g_dB1);
    cudaGetSymbolAddress((void**)&dw0,  g_dw0);
    cudaGetSymbolAddress((void**)&dw1,  g_dw1);

    static const int RQ_SMEM = CBK * 129 * sizeof(float);
    cudaFuncSetAttribute(rq_level, cudaFuncAttributeMaxDynamicSharedMemorySize, RQ_SMEM);

    // decoder weight table ([N,K] after transpose)
    const int dLN[4] = {512, 1024, 2048, 768};
    const int dLK[4] = {128, 512, 1024, 2048};
    size_t doff[4];
    {
        size_t o = 0;
        for (int i = 0; i < 4; i++) { doff[i] = o; o += (size_t)dLN[i] * dLK[i]; }
    }

    // ---- preprocess decoder weights ----
    for (int i = 0; i < 4; i++) {
        dim3 gd(dLN[i] / 32, dLK[i] / 32), b(32, 32);
        k_wprep2<<<gd, b>>>(dw[i], dw0 + doff[i], dw1 + doff[i], dLK[i], dLN[i]);
    }

    // ---- expert grouping ----
    k_zero_counts<<<1, 32>>>();
    k_hist   <<<BROWS / 256, 256>>>(labels);
    k_scan   <<<1, 1>>>();
    k_scatter<<<BROWS / 256, 256>>>(labels);

    // ---- encoder (fp32 f32x2 SIMT — bitwise-identical z) ----
    launch_sgemm<true >(x,    ew[0], eb[0], buf0, BROWS, 2048, 768);
    launch_sgemm<true >(buf0, ew[1], eb[1], buf1, BROWS, 1024, 2048);
    launch_sgemm<true >(buf1, ew[2], eb[2], buf0, BROWS, 512,  1024);
    launch_sgemm<false>(buf0, ew[3], eb[3], res,  BROWS, 128,  512);

    // ---- residual quantization ----
    k_rq_init<<<(BROWS * ZD + 255) / 256, 256>>>();
    dim3 rqg((BROWS + 31) / 32, NUM_EXPERTS);
    for (int l = 0; l < NUM_LEVELS; l++)
        rq_level<<<rqg, 256, RQ_SMEM>>>(cb, out + IDX_OFF, l);
    k_loss_finish<<<1, 1024>>>(out + LOSS_OFF);

    // ---- x_q output + decoder input split (fused) ----
    k_xq_out<<<(BROWS * ZD + 255) / 256, 256>>>(xq, out + XQ_OFF, dA0, dA1);

    // ---- decoder (bf16x3 HMMA, STAGES=2 -> 2 CTAs/SM) ----
    launch_hmma<2, true, 1>(dA0, dA1, dw0 + doff[0], dw1 + doff[0], db[0],
                            nullptr, dB0, dB1, BROWS, 512, 128);
    launch_hmma<2, true, 1>(dB0, dB1, dw0 + doff[1], dw1 + doff[1], db[1],
                            nullptr, dA0, dA1, BROWS, 1024, 512);
    launch_hmma<2, true, 1>(dA0, dA1, dw0 + doff[2], dw1 + doff[2], db[2],
                            nullptr, dB0, dB1, BROWS, 2048, 1024);
    launch_hmma<2, false, 0>(dB0, dB1, dw0 + doff[3], dw1 + doff[3], db[3],
                             out + OUT_OFF, nullptr, nullptr, BROWS, 768, 2048);
}

// round 12
// speedup vs baseline: 1.1397x; 1.0264x over previous
#include <cuda_runtime.h>
#include <cuda_bf16.h>
#include <cstdint>

// ---------------------------------------------------------------------------
// Problem constants
// ---------------------------------------------------------------------------
#define BROWS 32768
#define NUM_EXPERTS 10
#define NUM_LEVELS 4
#define CBK 256
#define ZD 128
#define BETA 0.001f

// Output layout (float32, tuple flattened: out, loss, indices, x_q)
#define OUT_OFF  0
#define LOSS_OFF (32768 * 768)
#define IDX_OFF  (LOSS_OFF + 1)
#define XQ_OFF   (IDX_OFF + 32768 * 4)

// ---------------------------------------------------------------------------
// Device scratch
// ---------------------------------------------------------------------------
__device__ float g_buf0[32768u * 2048u];   // encoder ping
__device__ float g_buf1[32768u * 1024u];   // encoder pong
__device__ float g_res [32768 * ZD];
__device__ float g_xq  [32768 * ZD];
__device__ float g_lossbuf[32768];
__device__ int   g_counts[NUM_EXPERTS];
__device__ int   g_cursor[NUM_EXPERTS];
__device__ int   g_offsets[NUM_EXPERTS + 1];
__device__ int   g_perm[32768];

// decoder bf16 hi/lo activation ping-pong + pre-split transposed weights
__device__ __nv_bfloat16 g_dA0[32768u * 1024u];
__device__ __nv_bfloat16 g_dA1[32768u * 1024u];
__device__ __nv_bfloat16 g_dB0[32768u * 2048u];
__device__ __nv_bfloat16 g_dB1[32768u * 2048u];
#define W_TOTAL 4259840
__device__ __nv_bfloat16 g_dw0[W_TOTAL];
__device__ __nv_bfloat16 g_dw1[W_TOTAL];

// ---------------------------------------------------------------------------
// PTX helpers
// ---------------------------------------------------------------------------
__device__ __forceinline__ uint32_t smem_u32(const void* p) {
    uint32_t a;
    asm("{ .reg .u64 t; cvta.to.shared.u64 t, %1; cvt.u32.u64 %0, t; }"
        : "=r"(a) : "l"(p));
    return a;
}
__device__ __forceinline__ void cpa16(uint32_t dst, const void* src) {
    asm volatile("cp.async.cg.shared.global [%0], [%1], 16;" :: "r"(dst), "l"(src) : "memory");
}
#define CP_COMMIT() asm volatile("cp.async.commit_group;" ::: "memory")
#define CP_WAIT(n)  asm volatile("cp.async.wait_group %0;" :: "n"(n) : "memory")

#define LDSM4(r0, r1, r2, r3, addr) \
    asm volatile("ldmatrix.sync.aligned.m8n8.x4.shared.b16 {%0,%1,%2,%3}, [%4];" \
        : "=r"(r0), "=r"(r1), "=r"(r2), "=r"(r3) : "r"(addr))

#define MMA16816(acc, a, b0, b1) \
    asm volatile("mma.sync.aligned.m16n8k16.row.col.f32.bf16.bf16.f32 " \
        "{%0,%1,%2,%3}, {%4,%5,%6,%7}, {%8,%9}, {%0,%1,%2,%3};" \
        : "+f"((acc)[0]), "+f"((acc)[1]), "+f"((acc)[2]), "+f"((acc)[3]) \
        : "r"((a)[0]), "r"((a)[1]), "r"((a)[2]), "r"((a)[3]), "r"(b0), "r"(b1))

// packed fp32 FMA (per-lane IEEE fma.rn)
#define FMA2(d, a, b) \
    asm("fma.rn.f32x2 %0, %1, %2, %0;" : "+l"(d) : "l"(a), "l"(b))
#define PACK2(out, x) \
    asm("mov.b64 %0, {%1, %1};" : "=l"(out) : "f"(x))
#define UNPACK2(lo, hi, in) \
    asm("mov.b64 {%0, %1}, %2;" : "=f"(lo), "=f"(hi) : "l"(in))

// ---------------------------------------------------------------------------
// fp32 SIMT SGEMM v4 — ENCODER. Same FMA set & per-element accumulation order
// as rounds 1/9/10/11 (bitwise-identical z). FFMA2 inner loop; B staged via
// cp.async (triple buffer) to free registers and issue slots; A keeps the
// register path (transposed smem layout).
// ---------------------------------------------------------------------------
template <bool RELU>
__global__ __launch_bounds__(256, 2)
void sgemm_db(const float* __restrict__ A, const float* __restrict__ W,
              const float* __restrict__ bias, float* __restrict__ C,
              int M, int N, int K)
{
    __shared__ float As[2][16][128];   // [stage][k][row]   (transposed, LDG path)
    __shared__ float Bs[3][16][128];   // [stage][k][col]   (cp.async path)

    const int t  = threadIdx.x;
    const int bm = blockIdx.y;
    const int bn = blockIdx.x;
    const int tx = t & 15;
    const int ty = t >> 4;

    const int ar0 = t >> 2;            // 0..63
    const int akq = (t & 3) * 4;       // 0,4,8,12
    const int bk0 = t >> 5;            // 0..7
    const int bcq = (t & 31) * 4;      // 0..124

    const float* Ag = A + (size_t)(bm * 128) * K;
    const float* Wg = W + bn * 128;

    const uint32_t bs_base0 = smem_u32(&Bs[0][bk0][bcq]);
    const uint32_t bs_base1 = smem_u32(&Bs[0][8 + bk0][bcq]);
    const uint32_t BS_STAGE = 16 * 128 * 4;

    unsigned long long acc2[8][4];     // [i][j-pair]; lanes = cols (2j, 2j+1)
#pragma unroll
    for (int i = 0; i < 8; i++)
#pragma unroll
        for (int j = 0; j < 4; j++) acc2[i][j] = 0ull;

    const int nch = K >> 4;

    // prologue: A chunk0 to regs; B chunks 0,1 via cp.async
    float4 pa0 = *(const float4*)(Ag + (size_t)ar0 * K + akq);
    float4 pa1 = *(const float4*)(Ag + (size_t)(64 + ar0) * K + akq);
    cpa16(bs_base0, Wg + (size_t)bk0 * N + bcq);
    cpa16(bs_base1, Wg + (size_t)(8 + bk0) * N + bcq);
    CP_COMMIT();
    if (nch > 1) {
        cpa16(bs_base0 + BS_STAGE, Wg + (size_t)(16 + bk0) * N + bcq);
        cpa16(bs_base1 + BS_STAGE, Wg + (size_t)(16 + 8 + bk0) * N + bcq);
    }
    CP_COMMIT();

    for (int ch = 0; ch < nch; ch++) {
        const int s  = ch & 1;
        const int bs = ch % 3;
        // store prefetched A chunk (transposed)
        As[s][akq + 0][ar0] = pa0.x;
        As[s][akq + 1][ar0] = pa0.y;
        As[s][akq + 2][ar0] = pa0.z;
        As[s][akq + 3][ar0] = pa0.w;
        As[s][akq + 0][64 + ar0] = pa1.x;
        As[s][akq + 1][64 + ar0] = pa1.y;
        As[s][akq + 2][64 + ar0] = pa1.z;
        As[s][akq + 3][64 + ar0] = pa1.w;
        CP_WAIT(1);                    // B chunk ch arrived
        __syncthreads();

        // issue B chunk ch+2 into stage (ch+2)%3 (read at ch-1, drained by sync)
        if (ch + 2 < nch) {
            const int k0 = (ch + 2) << 4;
            const uint32_t dst = (uint32_t)(((ch + 2) % 3) * BS_STAGE);
            cpa16(bs_base0 + dst, Wg + (size_t)(k0 + bk0) * N + bcq);
            cpa16(bs_base1 + dst, Wg + (size_t)(k0 + 8 + bk0) * N + bcq);
        }
        CP_COMMIT();
        // prefetch A chunk ch+1 to regs
        if (ch + 1 < nch) {
            const int k0 = (ch + 1) << 4;
            pa0 = *(const float4*)(Ag + (size_t)ar0 * K + k0 + akq);
            pa1 = *(const float4*)(Ag + (size_t)(64 + ar0) * K + k0 + akq);
        }

#pragma unroll
        for (int k = 0; k < 16; k++) {
            float a[8];
            *(float4*)&a[0] = *(const float4*)&As[s][k][ty * 8];
            *(float4*)&a[4] = *(const float4*)&As[s][k][ty * 8 + 4];
            const ulonglong2 b01 = *(const ulonglong2*)&Bs[bs][k][tx * 8];
            const ulonglong2 b23 = *(const ulonglong2*)&Bs[bs][k][tx * 8 + 4];
            unsigned long long bp[4] = {b01.x, b01.y, b23.x, b23.y};
            unsigned long long ap[8];
#pragma unroll
            for (int i = 0; i < 8; i++) PACK2(ap[i], a[i]);
#pragma unroll
            for (int i = 0; i < 8; i++)
#pragma unroll
                for (int j = 0; j < 4; j++)
                    FMA2(acc2[i][j], ap[i], bp[j]);
        }
    }

    const int crow0 = bm * 128 + ty * 8;
    const int ccol0 = bn * 128 + tx * 8;
    float bb[8];
#pragma unroll
    for (int j = 0; j < 8; j++) bb[j] = bias[ccol0 + j];

#pragma unroll
    for (int i = 0; i < 8; i++) {
        float v[8];
#pragma unroll
        for (int j = 0; j < 4; j++) {
            float lo, hi;
            UNPACK2(lo, hi, acc2[i][j]);
            float x0 = lo + bb[2 * j];
            float x1 = hi + bb[2 * j + 1];
            if (RELU) { x0 = fmaxf(x0, 0.f); x1 = fmaxf(x1, 0.f); }
            v[2 * j] = x0;
            v[2 * j + 1] = x1;
        }
        float* cp = C + (size_t)(crow0 + i) * N + ccol0;
        *(float4*)(cp)     = *(float4*)&v[0];
        *(float4*)(cp + 4) = *(float4*)&v[4];
    }
}

// ---------------------------------------------------------------------------
// HMMA bf16x3 GEMM — DECODER (unchanged: STAGES=2, 2 CTAs/SM).
// ---------------------------------------------------------------------------
#define TSTRIDE 40
#define SUBTILE (128 * TSTRIDE * 2)      // 10240 B

template <int STAGES, bool RELU, int OMODE>
__global__ __launch_bounds__(256)
void hmma_gemm(const __nv_bfloat16* __restrict__ A0, const __nv_bfloat16* __restrict__ A1,
               const __nv_bfloat16* __restrict__ B0, const __nv_bfloat16* __restrict__ B1,
               const float* __restrict__ bias, float* __restrict__ Cf,
               __nv_bfloat16* __restrict__ C0, __nv_bfloat16* __restrict__ C1,
               int M, int N, int K)
{
    constexpr int STAGE = 4 * SUBTILE;
    extern __shared__ char smem[];
    const uint32_t sbase = smem_u32(smem);

    const int tid  = threadIdx.x;
    const int lane = tid & 31;
    const int wid  = tid >> 5;
    const int wm   = wid & 3;
    const int wn   = wid >> 2;
    const int m0   = blockIdx.y * 128;
    const int n0   = blockIdx.x * 128;
    const int nch  = K >> 5;

    float acc[2][8][4];
#pragma unroll
    for (int a = 0; a < 2; a++)
#pragma unroll
        for (int b = 0; b < 8; b++)
#pragma unroll
            for (int c = 0; c < 4; c++) acc[a][b][c] = 0.f;

    auto load_stage = [&](int stg, int k0) {
        const uint32_t sb_ = sbase + stg * STAGE;
#pragma unroll
        for (int ii = 0; ii < 2; ii++) {
            const int i = tid + ii * 256;
            const int r = i >> 2, c = i & 3;
            const uint32_t so = r * 80 + c * 16;
            const size_t ga = (size_t)(m0 + r) * K + k0 + c * 8;
            const size_t gb = (size_t)(n0 + r) * K + k0 + c * 8;
            cpa16(sb_ + so,               A0 + ga);
            cpa16(sb_ + SUBTILE + so,     A1 + ga);
            cpa16(sb_ + 2 * SUBTILE + so, B0 + gb);
            cpa16(sb_ + 3 * SUBTILE + so, B1 + gb);
        }
    };

#pragma unroll
    for (int s = 0; s < STAGES; s++) {
        if (s < nch) load_stage(s, s * 32);
        CP_COMMIT();
    }

    const int lrow = lane & 15;
    const int lsel = (lane >> 4) << 3;

    for (int ch = 0; ch < nch; ch++) {
        CP_WAIT(STAGES - 1);
        __syncthreads();
        const uint32_t sb = sbase + (ch % STAGES) * STAGE;
        const uint32_t Ahb = sb, Alb = sb + SUBTILE;
        const uint32_t Bhb = sb + 2 * SUBTILE, Blb = sb + 3 * SUBTILE;

#pragma unroll
        for (int kk = 0; kk < 32; kk += 16) {
            uint32_t ah[2][4], al[2][4];
#pragma unroll
            for (int mt = 0; mt < 2; mt++) {
                uint32_t off = ((wm * 32 + mt * 16 + lrow) * TSTRIDE + kk + lsel) * 2;
                LDSM4(ah[mt][0], ah[mt][1], ah[mt][2], ah[mt][3], Ahb + off);
                LDSM4(al[mt][0], al[mt][1], al[mt][2], al[mt][3], Alb + off);
            }
            uint32_t bh[8][2], bl[8][2];
#pragma unroll
            for (int g = 0; g < 4; g++) {
                uint32_t off = ((wn * 64 + g * 16 + lrow) * TSTRIDE + kk + lsel) * 2;
                uint32_t t0, t1, t2, t3;
                LDSM4(t0, t1, t2, t3, Bhb + off);
                bh[2*g][0] = t0;   bh[2*g][1] = t2;
                bh[2*g+1][0] = t1; bh[2*g+1][1] = t3;
                LDSM4(t0, t1, t2, t3, Blb + off);
                bl[2*g][0] = t0;   bl[2*g][1] = t2;
                bl[2*g+1][0] = t1; bl[2*g+1][1] = t3;
            }
#pragma unroll
            for (int mt = 0; mt < 2; mt++)
#pragma unroll
                for (int nt = 0; nt < 8; nt++) {
                    MMA16816(acc[mt][nt], ah[mt], bh[nt][0], bh[nt][1]);
                    MMA16816(acc[mt][nt], ah[mt], bl[nt][0], bl[nt][1]);
                    MMA16816(acc[mt][nt], al[mt], bh[nt][0], bh[nt][1]);
                }
        }
        __syncthreads();
        if (ch + STAGES < nch) load_stage(ch % STAGES, (ch + STAGES) * 32);
        CP_COMMIT();
    }

    // ---- epilogue ----
    const int gid = lane >> 2;
    const int tg  = lane & 3;
#pragma unroll
    for (int mt = 0; mt < 2; mt++) {
#pragma unroll
        for (int nt = 0; nt < 8; nt++) {
            const int col = n0 + wn * 64 + nt * 8 + tg * 2;
            const float2 bb = __ldg((const float2*)(bias + col));
#pragma unroll
            for (int h = 0; h < 2; h++) {
                const int row = m0 + wm * 32 + mt * 16 + gid + h * 8;
                float v0 = acc[mt][nt][2*h]   + bb.x;
                float v1 = acc[mt][nt][2*h+1] + bb.y;
                if (RELU) { v0 = fmaxf(v0, 0.f); v1 = fmaxf(v1, 0.f); }
                if (OMODE == 0) {
                    *(float2*)(Cf + (size_t)row * N + col) = make_float2(v0, v1);
                } else {
                    __nv_bfloat16 h0 = __float2bfloat16(v0);
                    __nv_bfloat16 h1 = __float2bfloat16(v1);
                    __nv_bfloat162 p0; p0.x = h0; p0.y = h1;
                    __nv_bfloat162 p1;
                    p1.x = __float2bfloat16(v0 - __bfloat162float(h0));
                    p1.y = __float2bfloat16(v1 - __bfloat162float(h1));
                    *(__nv_bfloat162*)(C0 + (size_t)row * N + col) = p0;
                    *(__nv_bfloat162*)(C1 + (size_t)row * N + col) = p1;
                }
            }
        }
    }
}

// ---------------------------------------------------------------------------
// Preprocessing
// ---------------------------------------------------------------------------
__global__ void k_wprep2(const float* __restrict__ W, __nv_bfloat16* __restrict__ T0,
                         __nv_bfloat16* __restrict__ T1, int K, int N)
{
    __shared__ float t[32][33];
    int n = blockIdx.x * 32 + threadIdx.x;
    int k = blockIdx.y * 32 + threadIdx.y;
    t[threadIdx.y][threadIdx.x] = W[(size_t)k * N + n];
    __syncthreads();
    int nn = blockIdx.x * 32 + threadIdx.y;
    int kk = blockIdx.y * 32 + threadIdx.x;
    float v = t[threadIdx.x][threadIdx.y];
    __nv_bfloat16 h = __float2bfloat16(v);
    T0[(size_t)nn * K + kk] = h;
    T1[(size_t)nn * K + kk] = __float2bfloat16(v - __bfloat162float(h));
}

__global__ void k_xq_out(const float* __restrict__ xq, float* __restrict__ dst,
                         __nv_bfloat16* __restrict__ o0, __nv_bfloat16* __restrict__ o1)
{
    int i = blockIdx.x * 256 + threadIdx.x;
    if (i < BROWS * ZD) {
        float v = xq[i];
        dst[i] = v;
        __nv_bfloat16 h = __float2bfloat16(v);
        o0[i] = h;
        o1[i] = __float2bfloat16(v - __bfloat162float(h));
    }
}

// ---------------------------------------------------------------------------
// Expert counting-sort
// ---------------------------------------------------------------------------
__global__ void k_zero_counts() {
    int t = threadIdx.x;
    if (t < NUM_EXPERTS) { g_counts[t] = 0; g_cursor[t] = 0; }
}
__global__ void k_hist(const int* __restrict__ labels) {
    int i = blockIdx.x * blockDim.x + threadIdx.x;
    if (i < BROWS) atomicAdd(&g_counts[labels[i]], 1);
}
__global__ void k_scan() {
    if (threadIdx.x == 0) {
        int s = 0;
        for (int e = 0; e < NUM_EXPERTS; e++) { g_offsets[e] = s; s += g_counts[e]; }
        g_offsets[NUM_EXPERTS] = s;
    }
}
__global__ void k_scatter(const int* __restrict__ labels) {
    int i = blockIdx.x * blockDim.x + threadIdx.x;
    if (i < BROWS) {
        int e = labels[i];
        int p = atomicAdd(&g_cursor[e], 1);
        g_perm[g_offsets[e] + p] = i;
    }
}
__global__ void k_rq_init() {
    int i = blockIdx.x * blockDim.x + threadIdx.x;
    if (i < BROWS * ZD) g_xq[i] = 0.f;
    if (i < BROWS)      g_lossbuf[i] = 0.f;
}

// ---------------------------------------------------------------------------
// Residual quantization (R11 shuffle-argmin version — validated)
// ---------------------------------------------------------------------------
__global__ void rq_level(const float* __restrict__ cb,
                         float* __restrict__ idx_out, int level)
{
    extern __shared__ float c_sh[];        // 256 * 129 floats
    __shared__ float res_sh[ZD];
    __shared__ float cn_sh[CBK];
    __shared__ float s_ws[8];
    __shared__ int   s_wi[8];
    __shared__ float s_red[4];
    __shared__ int   s_kmin;

    const int e     = blockIdx.y;
    const int start = g_offsets[e];
    const int end   = g_offsets[e + 1];
    const int rbase = start + blockIdx.x * 32;
    if (rbase >= end) return;

    const int t = threadIdx.x;
    const int lane = t & 31;
    const int warp = t >> 5;

    const float* cbl = cb + ((size_t)level * NUM_EXPERTS + e) * CBK * ZD;
    for (int i = t; i < (CBK * ZD) / 4; i += 256) {
        float4 v = ((const float4*)cbl)[i];
        int k = i >> 5;
        int j = (i & 31) << 2;
        float* d = &c_sh[k * 129 + j];
        d[0] = v.x; d[1] = v.y; d[2] = v.z; d[3] = v.w;
    }
    __syncthreads();

    {
        const float* cr = &c_sh[t * 129];
        float s = 0.f;
#pragma unroll 8
        for (int j = 0; j < ZD; j++) s += cr[j] * cr[j];
        cn_sh[t] = s;
    }
    __syncthreads();

    const int nrows = min(32, end - rbase);
    for (int i = 0; i < nrows; i++) {
        const int row = g_perm[rbase + i];
        if (t < ZD) res_sh[t] = g_res[row * ZD + t];
        __syncthreads();

        float dot = 0.f;
        const float* cr = &c_sh[t * 129];
#pragma unroll 8
        for (int j = 0; j < ZD; j++) dot += cr[j] * res_sh[j];
        float sc = cn_sh[t] - 2.f * dot;
        int   ix = t;

#pragma unroll
        for (int o = 16; o > 0; o >>= 1) {
            float sc2 = __shfl_down_sync(0xffffffffu, sc, o);
            int   ix2 = __shfl_down_sync(0xffffffffu, ix, o);
            if (sc2 < sc || (sc2 == sc && ix2 < ix)) { sc = sc2; ix = ix2; }
        }
        if (lane == 0) { s_ws[warp] = sc; s_wi[warp] = ix; }
        __syncthreads();
        if (t == 0) {
            float bs = s_ws[0]; int bi = s_wi[0];
#pragma unroll
            for (int w = 1; w < 8; w++) {
                float s2 = s_ws[w]; int i2 = s_wi[w];
                if (s2 < bs || (s2 == bs && i2 < bi)) { bs = s2; bi = i2; }
            }
            s_kmin = bi;
        }
        __syncthreads();
        const int kmin = s_kmin;

        float sq = 0.f;
        if (t < ZD) {
            float q  = c_sh[kmin * 129 + t];
            float nr = res_sh[t] - q;
            g_res[row * ZD + t] = nr;
            g_xq [row * ZD + t] += q;
            sq = nr * nr;
        }
#pragma unroll
        for (int o = 16; o > 0; o >>= 1) sq += __shfl_down_sync(0xffffffffu, sq, o);
        if (t < ZD && lane == 0) s_red[warp] = sq;
        __syncthreads();
        if (t == 0) {
            g_lossbuf[row] += s_red[0] + s_red[1] + s_red[2] + s_red[3];
            idx_out[row * 4 + level] = (float)kmin;
        }
        __syncthreads();
    }
}

__global__ void k_loss_finish(float* __restrict__ loss_out) {
    __shared__ float sm[1024];
    float s = 0.f;
    for (int i = threadIdx.x; i < BROWS; i += 1024) s += g_lossbuf[i];
    sm[threadIdx.x] = s;
    __syncthreads();
    for (int k = 512; k > 0; k >>= 1) {
        if (threadIdx.x < k) sm[threadIdx.x] += sm[threadIdx.x + k];
        __syncthreads();
    }
    if (threadIdx.x == 0)
        loss_out[0] = sm[0] * (1.f + BETA) / ((float)BROWS * (float)ZD);
}

// ---------------------------------------------------------------------------
// Host launch
// ---------------------------------------------------------------------------
template <bool RELU>
static void launch_sgemm(const float* A, const float* W, const float* b, float* C,
                         int M, int N, int K)
{
    dim3 grid(N / 128, M / 128);
    sgemm_db<RELU><<<grid, 256>>>(A, W, b, C, M, N, K);
}

template <int STAGES, bool RELU, int OMODE>
static void launch_hmma(const __nv_bfloat16* a0, const __nv_bfloat16* a1,
                        const __nv_bfloat16* b0, const __nv_bfloat16* b1,
                        const float* bias, float* cf,
                        __nv_bfloat16* c0, __nv_bfloat16* c1,
                        int M, int N, int K)
{
    constexpr int SMEMB = STAGES * 4 * SUBTILE;
    cudaFuncSetAttribute(hmma_gemm<STAGES, RELU, OMODE>,
                         cudaFuncAttributeMaxDynamicSharedMemorySize, SMEMB);
    dim3 g(N / 128, M / 128);
    hmma_gemm<STAGES, RELU, OMODE><<<g, 256, SMEMB>>>(
        a0, a1, b0, b1, bias, cf, c0, c1, M, N, K);
}

extern "C" void kernel_launch(void* const* d_in, const int* in_sizes, int n_in,
                              void* d_out, int out_size)
{
    const float* x      = (const float*)d_in[0];
    const int*   labels = (const int*)  d_in[1];
    const float* ew[4]  = {(const float*)d_in[2], (const float*)d_in[4],
                           (const float*)d_in[6], (const float*)d_in[8]};
    const float* eb[4]  = {(const float*)d_in[3], (const float*)d_in[5],
                           (const float*)d_in[7], (const float*)d_in[9]};
    const float* dw[4]  = {(const float*)d_in[10], (const float*)d_in[12],
                           (const float*)d_in[14], (const float*)d_in[16]};
    const float* db[4]  = {(const float*)d_in[11], (const float*)d_in[13],
                           (const float*)d_in[15], (const float*)d_in[17]};
    const float* cb     = (const float*)d_in[18];
    float* out = (float*)d_out;

    float *buf0, *buf1, *res, *xq;
    __nv_bfloat16 *dA0, *dA1, *dB0, *dB1, *dw0, *dw1;
    cudaGetSymbolAddress((void**)&buf0, g_buf0);
    cudaGetSymbolAddress((void**)&buf1, g_buf1);
    cudaGetSymbolAddress((void**)&res,  g_res);
    cudaGetSymbolAddress((void**)&xq,   g_xq);
    cudaGetSymbolAddress((void**)&dA0,  g_dA0);
    cudaGetSymbolAddress((void**)&dA1,  g_dA1);
    cudaGetSymbolAddress((void**)&dB0,  g_dB0);
    cudaGetSymbolAddress((void**)&dB1,  g_dB1);
    cudaGetSymbolAddress((void**)&dw0,  g_dw0);
    cudaGetSymbolAddress((void**)&dw1,  g_dw1);

    static const int RQ_SMEM = CBK * 129 * sizeof(float);
    cudaFuncSetAttribute(rq_level, cudaFuncAttributeMaxDynamicSharedMemorySize, RQ_SMEM);

    // decoder weight table ([N,K] after transpose)
    const int dLN[4] = {512, 1024, 2048, 768};
    const int dLK[4] = {128, 512, 1024, 2048};
    size_t doff[4];
    {
        size_t o = 0;
        for (int i = 0; i < 4; i++) { doff[i] = o; o += (size_t)dLN[i] * dLK[i]; }
    }

    // ---- preprocess decoder weights ----
    for (int i = 0; i < 4; i++) {
        dim3 gd(dLN[i] / 32, dLK[i] / 32), b(32, 32);
        k_wprep2<<<gd, b>>>(dw[i], dw0 + doff[i], dw1 + doff[i], dLK[i], dLN[i]);
    }

    // ---- expert grouping ----
    k_zero_counts<<<1, 32>>>();
    k_hist   <<<BROWS / 256, 256>>>(labels);
    k_scan   <<<1, 1>>>();
    k_scatter<<<BROWS / 256, 256>>>(labels);

    // ---- encoder (fp32 f32x2 SIMT v4 — bitwise-identical z) ----
    launch_sgemm<true >(x,    ew[0], eb[0], buf0, BROWS, 2048, 768);
    launch_sgemm<true >(buf0, ew[1], eb[1], buf1, BROWS, 1024, 2048);
    launch_sgemm<true >(buf1, ew[2], eb[2], buf0, BROWS, 512,  1024);
    launch_sgemm<false>(buf0, ew[3], eb[3], res,  BROWS, 128,  512);

    // ---- residual quantization ----
    k_rq_init<<<(BROWS * ZD + 255) / 256, 256>>>();
    dim3 rqg((BROWS + 31) / 32, NUM_EXPERTS);
    for (int l = 0; l < NUM_LEVELS; l++)
        rq_level<<<rqg, 256, RQ_SMEM>>>(cb, out + IDX_OFF, l);
    k_loss_finish<<<1, 1024>>>(out + LOSS_OFF);

    // ---- x_q output + decoder input split (fused) ----
    k_xq_out<<<(BROWS * ZD + 255) / 256, 256>>>(xq, out + XQ_OFF, dA0, dA1);

    // ---- decoder (bf16x3 HMMA, STAGES=2 -> 2 CTAs/SM) ----
    launch_hmma<2, true, 1>(dA0, dA1, dw0 + doff[0], dw1 + doff[0], db[0],
                            nullptr, dB0, dB1, BROWS, 512, 128);
    launch_hmma<2, true, 1>(dB0, dB1, dw0 + doff[1], dw1 + doff[1], db[1],
                            nullptr, dA0, dA1, BROWS, 1024, 512);
    launch_hmma<2, true, 1>(dA0, dA1, dw0 + doff[2], dw1 + doff[2], db[2],
                            nullptr, dB0, dB1, BROWS, 2048, 1024);
    launch_hmma<2, false, 0>(dB0, dB1, dw0 + doff[3], dw1 + doff[3], db[3],
                             out + OUT_OFF, nullptr, nullptr, BROWS, 768, 2048);
}